// round 8
// baseline (speedup 1.0000x reference)
#include <cuda_runtime.h>
#include <cuda_bf16.h>
#include <math.h>

// ---------------- problem constants ----------------
#define BB   2
#define SS   2048
#define EE   512
#define HH   8
#define LL   4
#define DHH  64
#define MMF  128
#define AAX  3
#define NVOC 17
#define BHH  (BB*HH)      // 16
#define BSR  (BB*SS)      // 4096
#define NCH  (SS/128)     // 16
#define FFD  (4*EE)       // 2048

#define DNQ   0.3535533905932738f
#define RATIO 0.08838834764831845f
#define KEPS  1e-4f
#define DEPS  1e-6f

// ---------------- scratch ----------------
__device__ float g_x [BSR*EE];
__device__ float g_q [BSR*EE];
__device__ float g_k [BSR*EE];
__device__ float g_v [BSR*EE];
__device__ float g_o [BSR*EE];
__device__ float g_ff[BSR*FFD];
__device__ float g_qp[BHH*SS*MMF];
__device__ float g_kp[BHH*SS*MMF];
__device__ unsigned g_kmaxv[LL];
__device__ float g_Sc[BHH*NCH*MMF*DHH];
__device__ float g_Sp[BHH*NCH*MMF*DHH];
__device__ float g_zc[BHH*NCH*MMF];
__device__ float g_zp[BHH*NCH*MMF];
__device__ float g_mu[BSR];
__device__ float g_rs[BSR];
__device__ unsigned g_projh[LL*DHH*MMF];   // transposed [l][k][m], tf32 hi
__device__ unsigned g_projl[LL*DHH*MMF];   // transposed [l][k][m], tf32 lo

// ---------------- helpers ----------------
__device__ __forceinline__ unsigned f_enc(float f){
    unsigned u = __float_as_uint(f);
    return (u & 0x80000000u) ? ~u : (u | 0x80000000u);
}
__device__ __forceinline__ float f_dec(unsigned u){
    return (u & 0x80000000u) ? __uint_as_float(u & 0x7fffffffu) : __uint_as_float(~u);
}
__device__ __forceinline__ unsigned f2tf(float x){
    unsigned r; asm("cvt.rna.tf32.f32 %0, %1;" : "=r"(r) : "f"(x)); return r;
}

#define MMA_TF32(c, a, b) asm volatile( \
  "mma.sync.aligned.m16n8k8.row.col.f32.tf32.tf32.f32 " \
  "{%0,%1,%2,%3}, {%4,%5,%6,%7}, {%8,%9}, {%0,%1,%2,%3};" \
  : "+f"(c[0]),"+f"(c[1]),"+f"(c[2]),"+f"(c[3]) \
  : "r"(a[0]),"r"(a[1]),"r"(a[2]),"r"(a[3]), "r"(b[0]),"r"(b[1]))

__device__ __forceinline__ void tfsplit(float x, unsigned& hi, unsigned& lo){
    hi = f2tf(x);
    lo = f2tf(x - __uint_as_float(hi));
}

// ---------------- embedding (+ per-layer kmax reset) ----------------
__global__ void embed_kernel(const int* __restrict__ value, const int* __restrict__ depth,
                             const int* __restrict__ pos,   const float* __restrict__ sos,
                             const float* __restrict__ tok, const float* __restrict__ dep,
                             const float* __restrict__ spa)
{
    if (blockIdx.x == 0 && threadIdx.x < LL) g_kmaxv[threadIdx.x] = 0u;
    int i = blockIdx.x * 256 + threadIdx.x;
    if (i >= BSR*EE) return;
    int e = i & (EE-1);
    int r = i >> 9;
    int b = r / SS, s = r - b*SS;
    float val;
    if (s == 0) val = sos[e];
    else {
        int p = b*SS + s - 1;
        val = tok[value[p]*EE + e] + dep[depth[p]*EE + e];
        #pragma unroll
        for (int a = 0; a < AAX; a++)
            val += spa[(size_t)a*65*EE + pos[p*AAX + a]*EE + e];
    }
    g_x[i] = val;
}

// ---------------- proj precompute: transposed hi/lo splits ----------------
__global__ void prep_proj_kernel(const float* __restrict__ proj)
{
    int i = blockIdx.x * 256 + threadIdx.x;      // i over LL*DHH*MMF
    if (i >= LL*DHH*MMF) return;
    int l = i / (DHH*MMF);
    int rem = i - l*(DHH*MMF);
    int k = rem >> 7;            // 0..63
    int m = rem & 127;           // 0..127
    float v = proj[(size_t)l*MMF*DHH + m*DHH + k];
    unsigned hi, lo; tfsplit(v, hi, lo);
    g_projh[i] = hi;
    g_projl[i] = lo;
}

// ---------------- layernorm stats (mu, rstd per row) ----------------
__global__ __launch_bounds__(128) void ln_stats_kernel(const float* __restrict__ in)
{
    int r = blockIdx.x, t = threadIdx.x;
    const float4 v = ((const float4*)(in + (size_t)r*EE))[t];
    float s  = v.x + v.y + v.z + v.w;
    float sq = v.x*v.x + v.y*v.y + v.z*v.z + v.w*v.w;
    #pragma unroll
    for (int o = 16; o; o >>= 1){ s += __shfl_xor_sync(~0u, s, o); sq += __shfl_xor_sync(~0u, sq, o); }
    __shared__ float sh[8];
    if ((t & 31) == 0){ sh[t>>5] = s; sh[4 + (t>>5)] = sq; }
    __syncthreads();
    if (t == 0){
        s  = sh[0]+sh[1]+sh[2]+sh[3];
        sq = sh[4]+sh[5]+sh[6]+sh[7];
        float mu  = s * (1.f/EE);
        float var = sq * (1.f/EE) - mu*mu;
        g_mu[r] = mu;
        g_rs[r] = rsqrtf(var + 1e-5f);
    }
}

// ---------------- tf32 GEMM (weights); optional fused LN on A ----------------
#define BKK 16
#define LDA 136
#define LDB 136

__device__ __forceinline__ float4 ln_apply(float4 a, float mu, float rs,
                                           const float* __restrict__ w,
                                           const float* __restrict__ b, int c0)
{
    float4 w4 = *(const float4*)&w[c0];
    float4 b4 = *(const float4*)&b[c0];
    a.x = (a.x - mu)*rs*w4.x + b4.x;
    a.y = (a.y - mu)*rs*w4.y + b4.y;
    a.z = (a.z - mu)*rs*w4.z + b4.z;
    a.w = (a.w - mu)*rs*w4.w + b4.w;
    return a;
}

__device__ __forceinline__ void gemm_body(
    const float* __restrict__ Am, const float* __restrict__ Bm,
    const float* __restrict__ bias, const float* __restrict__ resid,
    const float* __restrict__ lnw, const float* __restrict__ lnb,
    float* __restrict__ C, int N, int K, int act,
    unsigned* As, unsigned* Bs)
{
    const int tid = threadIdx.x;
    const int bm = blockIdx.y * 128, bn = blockIdx.x * 128;
    const int w = tid >> 5, lane = tid & 31;
    const int wm = (w & 1) * 64, wn = (w >> 1) * 32;
    const int lr = lane >> 2, lc = lane & 3;

    float acc[4][4][4];
    #pragma unroll
    for (int i = 0; i < 4; i++)
        #pragma unroll
        for (int j = 0; j < 4; j++)
            #pragma unroll
            for (int t = 0; t < 4; t++) acc[i][j][t] = 0.f;

    const int f0 = tid, f1 = tid + 256;
    const int ar0 = f0 >> 2, ak0 = (f0 & 3) << 2;
    const int ar1 = f1 >> 2, ak1 = (f1 & 3) << 2;
    const int br0 = f0 >> 5, bc0 = (f0 & 31) << 2;
    const int br1 = f1 >> 5, bc1 = (f1 & 31) << 2;

    const bool fuse = (lnw != nullptr);
    float mu0 = 0.f, rs0 = 1.f, mu1 = 0.f, rs1 = 1.f;
    if (fuse){
        mu0 = g_mu[bm + ar0]; rs0 = g_rs[bm + ar0];
        mu1 = g_mu[bm + ar1]; rs1 = g_rs[bm + ar1];
    }

    float4 a4[2], b4[2];
    const int nk = K / BKK;

    a4[0] = *(const float4*)&Am[(size_t)(bm + ar0)*K + ak0];
    a4[1] = *(const float4*)&Am[(size_t)(bm + ar1)*K + ak1];
    if (fuse){
        a4[0] = ln_apply(a4[0], mu0, rs0, lnw, lnb, ak0);
        a4[1] = ln_apply(a4[1], mu1, rs1, lnw, lnb, ak1);
    }
    b4[0] = *(const float4*)&Bm[(size_t)br0*N + bn + bc0];
    b4[1] = *(const float4*)&Bm[(size_t)br1*N + bn + bc1];
    {
        unsigned* Ab = As; unsigned* Bb = Bs;
        Ab[(ak0+0)*LDA + ar0] = f2tf(a4[0].x); Ab[(ak0+1)*LDA + ar0] = f2tf(a4[0].y);
        Ab[(ak0+2)*LDA + ar0] = f2tf(a4[0].z); Ab[(ak0+3)*LDA + ar0] = f2tf(a4[0].w);
        Ab[(ak1+0)*LDA + ar1] = f2tf(a4[1].x); Ab[(ak1+1)*LDA + ar1] = f2tf(a4[1].y);
        Ab[(ak1+2)*LDA + ar1] = f2tf(a4[1].z); Ab[(ak1+3)*LDA + ar1] = f2tf(a4[1].w);
        uint4 bv0 = make_uint4(f2tf(b4[0].x), f2tf(b4[0].y), f2tf(b4[0].z), f2tf(b4[0].w));
        uint4 bv1 = make_uint4(f2tf(b4[1].x), f2tf(b4[1].y), f2tf(b4[1].z), f2tf(b4[1].w));
        *(uint4*)&Bb[br0*LDB + bc0] = bv0;
        *(uint4*)&Bb[br1*LDB + bc1] = bv1;
    }
    __syncthreads();

    for (int it = 0; it < nk; it++){
        const int cur = it & 1;
        if (it + 1 < nk){
            const int k0 = (it + 1) * BKK;
            a4[0] = *(const float4*)&Am[(size_t)(bm + ar0)*K + k0 + ak0];
            a4[1] = *(const float4*)&Am[(size_t)(bm + ar1)*K + k0 + ak1];
            if (fuse){
                a4[0] = ln_apply(a4[0], mu0, rs0, lnw, lnb, k0 + ak0);
                a4[1] = ln_apply(a4[1], mu1, rs1, lnw, lnb, k0 + ak1);
            }
            b4[0] = *(const float4*)&Bm[(size_t)(k0 + br0)*N + bn + bc0];
            b4[1] = *(const float4*)&Bm[(size_t)(k0 + br1)*N + bn + bc1];
        }
        {
            const unsigned* Ab = As + cur * (BKK * LDA);
            const unsigned* Bb = Bs + cur * (BKK * LDB);
            #pragma unroll
            for (int ks = 0; ks < BKK; ks += 8){
                unsigned af[4][4], bf[4][2];
                #pragma unroll
                for (int mt = 0; mt < 4; mt++){
                    const int base = (ks + lc)*LDA + wm + mt*16 + lr;
                    af[mt][0] = Ab[base];
                    af[mt][1] = Ab[base + 8];
                    af[mt][2] = Ab[base + 4*LDA];
                    af[mt][3] = Ab[base + 4*LDA + 8];
                }
                #pragma unroll
                for (int nt = 0; nt < 4; nt++){
                    const int base = (ks + lc)*LDB + wn + nt*8 + lr;
                    bf[nt][0] = Bb[base];
                    bf[nt][1] = Bb[base + 4*LDB];
                }
                #pragma unroll
                for (int mt = 0; mt < 4; mt++)
                    #pragma unroll
                    for (int nt = 0; nt < 4; nt++)
                        MMA_TF32(acc[mt][nt], af[mt], bf[nt]);
            }
        }
        if (it + 1 < nk){
            unsigned* Ab = As + (cur ^ 1) * (BKK * LDA);
            unsigned* Bb = Bs + (cur ^ 1) * (BKK * LDB);
            Ab[(ak0+0)*LDA + ar0] = f2tf(a4[0].x); Ab[(ak0+1)*LDA + ar0] = f2tf(a4[0].y);
            Ab[(ak0+2)*LDA + ar0] = f2tf(a4[0].z); Ab[(ak0+3)*LDA + ar0] = f2tf(a4[0].w);
            Ab[(ak1+0)*LDA + ar1] = f2tf(a4[1].x); Ab[(ak1+1)*LDA + ar1] = f2tf(a4[1].y);
            Ab[(ak1+2)*LDA + ar1] = f2tf(a4[1].z); Ab[(ak1+3)*LDA + ar1] = f2tf(a4[1].w);
            uint4 bv0 = make_uint4(f2tf(b4[0].x), f2tf(b4[0].y), f2tf(b4[0].z), f2tf(b4[0].w));
            uint4 bv1 = make_uint4(f2tf(b4[1].x), f2tf(b4[1].y), f2tf(b4[1].z), f2tf(b4[1].w));
            *(uint4*)&Bb[br0*LDB + bc0] = bv0;
            *(uint4*)&Bb[br1*LDB + bc1] = bv1;
        }
        __syncthreads();
    }

    #pragma unroll
    for (int mt = 0; mt < 4; mt++){
        const int r0 = bm + wm + mt*16 + lr;
        #pragma unroll
        for (int nt = 0; nt < 4; nt++){
            const int c0 = bn + wn + nt*8 + 2*lc;
            const float bx = bias[c0], by = bias[c0+1];
            #pragma unroll
            for (int half = 0; half < 2; half++){
                const int r = r0 + half*8;
                float v0 = acc[mt][nt][half*2+0] + bx;
                float v1 = acc[mt][nt][half*2+1] + by;
                if (act){
                    v0 = 0.5f*v0*(1.f + erff(v0*0.70710678118654752f));
                    v1 = 0.5f*v1*(1.f + erff(v1*0.70710678118654752f));
                }
                if (resid){
                    v0 += resid[(size_t)r*N + c0];
                    v1 += resid[(size_t)r*N + c0+1];
                }
                *(float2*)&C[(size_t)r*N + c0] = make_float2(v0, v1);
            }
        }
    }
}

__global__ __launch_bounds__(256, 2) void tgemm_kernel(
    const float* __restrict__ A, const float* __restrict__ Bm,
    const float* __restrict__ bias, const float* __restrict__ resid,
    const float* __restrict__ lnw, const float* __restrict__ lnb,
    float* __restrict__ C, int N, int K, int act)
{
    __shared__ __align__(16) unsigned As[2*BKK*LDA];
    __shared__ __align__(16) unsigned Bs[2*BKK*LDB];
    gemm_body(A, Bm, bias, resid, lnw, lnb, C, N, K, act, As, Bs);
}

__global__ __launch_bounds__(256, 2) void qkv_kernel(
    const float* __restrict__ A,
    const float* __restrict__ Wq, const float* __restrict__ Wk, const float* __restrict__ Wv,
    const float* __restrict__ bq, const float* __restrict__ bk, const float* __restrict__ bv,
    const float* __restrict__ lnw, const float* __restrict__ lnb,
    float* __restrict__ oq, float* __restrict__ ok, float* __restrict__ ov)
{
    __shared__ __align__(16) unsigned As[2*BKK*LDA];
    __shared__ __align__(16) unsigned Bs[2*BKK*LDB];
    const int z = blockIdx.z;
    const float* Bm  = (z == 0) ? Wq : (z == 1) ? Wk : Wv;
    const float* bi  = (z == 0) ? bq : (z == 1) ? bk : bv;
    float*       Cm  = (z == 0) ? oq : (z == 1) ? ok : ov;
    gemm_body(A, Bm, bi, nullptr, lnw, lnb, Cm, EE, EE, 0, As, Bs);
}

// ================= FAVOR features via 3xTF32 MMA =================
__global__ __launch_bounds__(256) void feat_kernel(int l)
{
    __shared__ unsigned Ah[16*LDA], Al[16*LDA], Bh[16*LDB], Bl[16*LDB];
    __shared__ float diag[128];
    __shared__ unsigned rmax[128];
    __shared__ unsigned bmax;
    const int tid = threadIdx.x;
    const int c = blockIdx.x, bh = blockIdx.y;
    const int isq = (blockIdx.z == 0);
    const int b = bh / HH, h = bh % HH;
    const float* src = isq ? g_q : g_k;
    const unsigned* prjh = g_projh + (size_t)l*DHH*MMF;
    const unsigned* prjl = g_projl + (size_t)l*DHH*MMF;
    const int w = tid >> 5, lane = tid & 31;
    const int wm = (w & 1) * 64, wn = (w >> 1) * 32;
    const int lr = lane >> 2, lc = lane & 3;

    if (tid < 128) rmax[tid] = 0u;
    if (tid == 0) bmax = 0u;

    float acc[4][4][4];
    #pragma unroll
    for (int i = 0; i < 4; i++)
        #pragma unroll
        for (int j = 0; j < 4; j++)
            #pragma unroll
            for (int t = 0; t < 4; t++) acc[i][j][t] = 0.f;

    const int rrow = tid >> 1, kg = (tid & 1) * 8;
    const int bk = tid >> 4, bm0 = (tid & 15) * 8;     // B staging (transposed layout)
    float sq = 0.f;

    for (int kit = 0; kit < 4; kit++){
        const int k0 = kit * 16;
        // A: x rows (scaled) — staged k-major with tfsplit
        #pragma unroll
        for (int q4 = 0; q4 < 2; q4++){
            float4 a = *(const float4*)&src[((size_t)(b*SS + c*128 + rrow))*EE + h*DHH + k0 + kg + q4*4];
            float vals[4] = {a.x*DNQ, a.y*DNQ, a.z*DNQ, a.w*DNQ};
            #pragma unroll
            for (int i = 0; i < 4; i++){
                sq += vals[i]*vals[i];
                unsigned hi, lo; tfsplit(vals[i], hi, lo);
                Ah[(kg + q4*4 + i)*LDA + rrow] = hi;
                Al[(kg + q4*4 + i)*LDA + rrow] = lo;
            }
        }
        // B: precomputed transposed hi/lo proj — vector copies
        {
            const size_t pb = (size_t)(k0 + bk)*MMF + bm0;
            uint4 h0 = *(const uint4*)&prjh[pb];
            uint4 h1 = *(const uint4*)&prjh[pb + 4];
            uint4 l0 = *(const uint4*)&prjl[pb];
            uint4 l1 = *(const uint4*)&prjl[pb + 4];
            *(uint4*)&Bh[bk*LDB + bm0]     = h0;
            *(uint4*)&Bh[bk*LDB + bm0 + 4] = h1;
            *(uint4*)&Bl[bk*LDB + bm0]     = l0;
            *(uint4*)&Bl[bk*LDB + bm0 + 4] = l1;
        }
        __syncthreads();
        #pragma unroll
        for (int ks = 0; ks < 16; ks += 8){
            unsigned afh[4][4], afl[4][4], bfh[4][2], bfl[4][2];
            #pragma unroll
            for (int mt = 0; mt < 4; mt++){
                const int base = (ks + lc)*LDA + wm + mt*16 + lr;
                afh[mt][0] = Ah[base];        afl[mt][0] = Al[base];
                afh[mt][1] = Ah[base + 8];    afl[mt][1] = Al[base + 8];
                afh[mt][2] = Ah[base + 4*LDA];afl[mt][2] = Al[base + 4*LDA];
                afh[mt][3] = Ah[base + 4*LDA + 8]; afl[mt][3] = Al[base + 4*LDA + 8];
            }
            #pragma unroll
            for (int nt = 0; nt < 4; nt++){
                const int base = (ks + lc)*LDB + wn + nt*8 + lr;
                bfh[nt][0] = Bh[base];         bfl[nt][0] = Bl[base];
                bfh[nt][1] = Bh[base + 4*LDB]; bfl[nt][1] = Bl[base + 4*LDB];
            }
            #pragma unroll
            for (int mt = 0; mt < 4; mt++)
                #pragma unroll
                for (int nt = 0; nt < 4; nt++){
                    MMA_TF32(acc[mt][nt], afh[mt], bfh[nt]);
                    MMA_TF32(acc[mt][nt], afh[mt], bfl[nt]);
                    MMA_TF32(acc[mt][nt], afl[mt], bfh[nt]);
                }
        }
        __syncthreads();
    }
    {
        float other = __shfl_xor_sync(~0u, sq, 1);
        if ((tid & 1) == 0) diag[rrow] = 0.5f * (sq + other);
    }
    if (isq){
        #pragma unroll
        for (int mt = 0; mt < 4; mt++)
            #pragma unroll
            for (int half = 0; half < 2; half++){
                const int r = wm + mt*16 + lr + half*8;
                float m = -3.4e38f;
                #pragma unroll
                for (int nt = 0; nt < 4; nt++){
                    m = fmaxf(m, acc[mt][nt][half*2+0]);
                    m = fmaxf(m, acc[mt][nt][half*2+1]);
                }
                atomicMax(&rmax[r], f_enc(m));
            }
    } else {
        float m = -3.4e38f;
        #pragma unroll
        for (int mt = 0; mt < 4; mt++)
            #pragma unroll
            for (int nt = 0; nt < 4; nt++)
                #pragma unroll
                for (int t = 0; t < 4; t++) m = fmaxf(m, acc[mt][nt][t]);
        #pragma unroll
        for (int o = 16; o; o >>= 1) m = fmaxf(m, __shfl_xor_sync(~0u, m, o));
        if (lane == 0) atomicMax(&bmax, f_enc(m));
    }
    __syncthreads();

    const size_t qbase = (size_t)bh*SS + c*128;
    if (isq){
        #pragma unroll
        for (int mt = 0; mt < 4; mt++)
            #pragma unroll
            for (int half = 0; half < 2; half++){
                const int r = wm + mt*16 + lr + half*8;
                const float dg = diag[r], mx = f_dec(rmax[r]);
                #pragma unroll
                for (int nt = 0; nt < 4; nt++){
                    const int c0 = wn + nt*8 + 2*lc;
                    float v0 = RATIO*(expf(acc[mt][nt][half*2+0] - dg - mx) + KEPS);
                    float v1 = RATIO*(expf(acc[mt][nt][half*2+1] - dg - mx) + KEPS);
                    *(float2*)&g_qp[(qbase + r)*MMF + c0] = make_float2(v0, v1);
                }
            }
    } else {
        if (tid == 0) atomicMax(&g_kmaxv[l], bmax);
        #pragma unroll
        for (int mt = 0; mt < 4; mt++)
            #pragma unroll
            for (int half = 0; half < 2; half++){
                const int r = wm + mt*16 + lr + half*8;
                const float dg = diag[r];
                #pragma unroll
                for (int nt = 0; nt < 4; nt++){
                    const int c0 = wn + nt*8 + 2*lc;
                    float v0 = acc[mt][nt][half*2+0] - dg;
                    float v1 = acc[mt][nt][half*2+1] - dg;
                    *(float2*)&g_kp[(qbase + r)*MMF + c0] = make_float2(v0, v1);
                }
            }
    }
}

// ========== fused: kp exp-transform + writeback + zc + Sc (3xTF32 MMA) ==========
#define KVLDB 72
__global__ __launch_bounds__(256, 2) void kvz_kernel(int l)
{
    __shared__ unsigned Ah[16*LDA], Al[16*LDA], Bh[16*KVLDB], Bl[16*KVLDB];
    __shared__ float zcs[128];
    const int c = blockIdx.x, bh = blockIdx.y;
    const int b = bh / HH, h = bh % HH;
    const int tid = threadIdx.x;
    const int w = tid >> 5, lane = tid & 31;
    const int wm = (w & 1) * 64, wn = (w >> 1) * 16;
    const int lr = lane >> 2, lc = lane & 3;
    const size_t qbase = (size_t)bh*SS + c*128;
    const float gm = f_dec(g_kmaxv[l]);

    if (tid < 128) zcs[tid] = 0.f;

    float acc[4][2][4];
    #pragma unroll
    for (int i = 0; i < 4; i++)
        #pragma unroll
        for (int j = 0; j < 2; j++)
            #pragma unroll
            for (int t = 0; t < 4; t++) acc[i][j][t] = 0.f;

    const int at = tid >> 4, am0 = (tid & 15) * 8;
    const int bt = tid >> 4, bd0 = (tid & 15) * 4;
    float zcp[8];
    #pragma unroll
    for (int i = 0; i < 8; i++) zcp[i] = 0.f;

    for (int kit = 0; kit < 8; kit++){
        const int t0 = kit * 16;
        #pragma unroll
        for (int q4 = 0; q4 < 2; q4++){
            size_t off = (qbase + t0 + at)*MMF + am0 + q4*4;
            float4 a = *(const float4*)&g_kp[off];
            float vals[4];
            vals[0] = RATIO*(expf(a.x - gm) + KEPS);
            vals[1] = RATIO*(expf(a.y - gm) + KEPS);
            vals[2] = RATIO*(expf(a.z - gm) + KEPS);
            vals[3] = RATIO*(expf(a.w - gm) + KEPS);
            *(float4*)&g_kp[off] = make_float4(vals[0], vals[1], vals[2], vals[3]);
            #pragma unroll
            for (int i = 0; i < 4; i++){
                zcp[q4*4 + i] += vals[i];
                unsigned hi, lo; tfsplit(vals[i], hi, lo);
                Ah[at*LDA + am0 + q4*4 + i] = hi;
                Al[at*LDA + am0 + q4*4 + i] = lo;
            }
        }
        {
            float4 vv = *(const float4*)&g_v[((size_t)(b*SS + c*128 + t0 + bt))*EE + h*DHH + bd0];
            float vals[4] = {vv.x, vv.y, vv.z, vv.w};
            #pragma unroll
            for (int i = 0; i < 4; i++){
                unsigned hi, lo; tfsplit(vals[i], hi, lo);
                Bh[bt*KVLDB + bd0 + i] = hi;
                Bl[bt*KVLDB + bd0 + i] = lo;
            }
        }
        __syncthreads();
        #pragma unroll
        for (int ks = 0; ks < 16; ks += 8){
            unsigned afh[4][4], afl[4][4], bfh[2][2], bfl[2][2];
            #pragma unroll
            for (int mt = 0; mt < 4; mt++){
                const int base = (ks + lc)*LDA + wm + mt*16 + lr;
                afh[mt][0] = Ah[base];         afl[mt][0] = Al[base];
                afh[mt][1] = Ah[base + 8];     afl[mt][1] = Al[base + 8];
                afh[mt][2] = Ah[base + 4*LDA]; afl[mt][2] = Al[base + 4*LDA];
                afh[mt][3] = Ah[base + 4*LDA + 8]; afl[mt][3] = Al[base + 4*LDA + 8];
            }
            #pragma unroll
            for (int nt = 0; nt < 2; nt++){
                const int base = (ks + lc)*KVLDB + wn + nt*8 + lr;
                bfh[nt][0] = Bh[base];           bfl[nt][0] = Bl[base];
                bfh[nt][1] = Bh[base + 4*KVLDB]; bfl[nt][1] = Bl[base + 4*KVLDB];
            }
            #pragma unroll
            for (int mt = 0; mt < 4; mt++)
                #pragma unroll
                for (int nt = 0; nt < 2; nt++){
                    MMA_TF32(acc[mt][nt], afh[mt], bfh[nt]);
                    MMA_TF32(acc[mt][nt], afh[mt], bfl[nt]);
                    MMA_TF32(acc[mt][nt], afl[mt], bfh[nt]);
                }
        }
        __syncthreads();
    }
    #pragma unroll
    for (int i = 0; i < 8; i++) atomicAdd(&zcs[am0 + i], zcp[i]);
    __syncthreads();
    if (tid < 128) g_zc[(bh*NCH + c)*MMF + tid] = zcs[tid];

    const size_t base = ((size_t)(bh*NCH + c))*MMF;
    #pragma unroll
    for (int mt = 0; mt < 4; mt++)
        #pragma unroll
        for (int half = 0; half < 2; half++){
            const int m = wm + mt*16 + lr + half*8;
            #pragma unroll
            for (int nt = 0; nt < 2; nt++){
                const int d0 = wn + nt*8 + 2*lc;
                *(float2*)&g_Sc[(base + m)*DHH + d0] =
                    make_float2(acc[mt][nt][half*2+0], acc[mt][nt][half*2+1]);
            }
        }
}

// ---------------- parallel exclusive prefix over chunks ----------------
__global__ __launch_bounds__(1024) void chunk_prefix_kernel()
{
    const int bh = blockIdx.y;
    const int idx = blockIdx.x * 1024 + threadIdx.x;
    float run = 0.f;
    #pragma unroll
    for (int c = 0; c < NCH; c++){
        size_t off = ((size_t)(bh*NCH + c))*MMF*DHH + idx;
        float v = g_Sc[off];
        g_Sp[off] = run;
        run += v;
    }
    if (blockIdx.x == 0 && threadIdx.x < MMF){
        const int m = threadIdx.x;
        float rz = 0.f;
        #pragma unroll
        for (int c = 0; c < NCH; c++){
            int zb = (bh*NCH + c)*MMF + m;
            g_zp[zb] = rz;
            rz += g_zc[zb];
        }
    }
}

// ======= FUSED: P = mask(qp@kp^T) in smem, then out = ([P|qp]@[v;Sp])/den =======
#define LDP 132
#define PO_PS_WORDS (128*LDP)          // 16896
#define PO_AB_WORDS (16*LDA)           // 2176
#define PO_SMEM_BYTES ((PO_PS_WORDS + 4*PO_AB_WORDS + 128) * 4)   // 102912 B

__global__ __launch_bounds__(256) void po_kernel()
{
    extern __shared__ __align__(16) float po_smem[];
    float*    Ps    = po_smem;
    unsigned* Ah    = (unsigned*)(po_smem + PO_PS_WORDS);
    unsigned* Al    = Ah + PO_AB_WORDS;
    unsigned* Bh    = Al + PO_AB_WORDS;
    unsigned* Bl    = Bh + PO_AB_WORDS;
    float*    densh = (float*)(Bl + PO_AB_WORDS);

    const int c = blockIdx.x, bh = blockIdx.y;
    const int b = bh / HH, h = bh % HH;
    const int tid = threadIdx.x;
    const int w = tid >> 5, lane = tid & 31;
    const int wm = (w & 1) * 64;
    const int wnp = (w >> 1) * 32;
    const int wno = (w >> 1) * 16;
    const int lr = lane >> 2, lc = lane & 3;
    const size_t qbase = (size_t)bh*SS + c*128;
    const size_t sbase = ((size_t)(bh*NCH + c))*MMF;
    const int rrow = tid >> 1, kg = (tid & 1) * 8;

    // ---------------- phase 1: P = mask(qp @ kp^T) ----------------
    {
        float acc[4][4][4];
        #pragma unroll
        for (int i = 0; i < 4; i++)
            #pragma unroll
            for (int j = 0; j < 4; j++)
                #pragma unroll
                for (int t = 0; t < 4; t++) acc[i][j][t] = 0.f;

        for (int kit = 0; kit < 8; kit++){
            const int m0 = kit * 16;
            #pragma unroll
            for (int q4 = 0; q4 < 2; q4++){
                float4 a = *(const float4*)&g_qp[(qbase + rrow)*MMF + m0 + kg + q4*4];
                float va[4] = {a.x, a.y, a.z, a.w};
                float4 bk = *(const float4*)&g_kp[(qbase + rrow)*MMF + m0 + kg + q4*4];
                float vb[4] = {bk.x, bk.y, bk.z, bk.w};
                #pragma unroll
                for (int i = 0; i < 4; i++){
                    unsigned hi, lo;
                    tfsplit(va[i], hi, lo);
                    Ah[(kg + q4*4 + i)*LDA + rrow] = hi;
                    Al[(kg + q4*4 + i)*LDA + rrow] = lo;
                    tfsplit(vb[i], hi, lo);
                    Bh[(kg + q4*4 + i)*LDB + rrow] = hi;
                    Bl[(kg + q4*4 + i)*LDB + rrow] = lo;
                }
            }
            __syncthreads();
            #pragma unroll
            for (int ks = 0; ks < 16; ks += 8){
                unsigned afh[4][4], afl[4][4], bfh[4][2], bfl[4][2];
                #pragma unroll
                for (int mt = 0; mt < 4; mt++){
                    const int base = (ks + lc)*LDA + wm + mt*16 + lr;
                    afh[mt][0] = Ah[base];         afl[mt][0] = Al[base];
                    afh[mt][1] = Ah[base + 8];     afl[mt][1] = Al[base + 8];
                    afh[mt][2] = Ah[base + 4*LDA]; afl[mt][2] = Al[base + 4*LDA];
                    afh[mt][3] = Ah[base + 4*LDA + 8]; afl[mt][3] = Al[base + 4*LDA + 8];
                }
                #pragma unroll
                for (int nt = 0; nt < 4; nt++){
                    const int base = (ks + lc)*LDB + wnp + nt*8 + lr;
                    bfh[nt][0] = Bh[base];         bfl[nt][0] = Bl[base];
                    bfh[nt][1] = Bh[base + 4*LDB]; bfl[nt][1] = Bl[base + 4*LDB];
                }
                #pragma unroll
                for (int mt = 0; mt < 4; mt++)
                    #pragma unroll
                    for (int nt = 0; nt < 4; nt++){
                        MMA_TF32(acc[mt][nt], afh[mt], bfh[nt]);
                        MMA_TF32(acc[mt][nt], afh[mt], bfl[nt]);
                        MMA_TF32(acc[mt][nt], afl[mt], bfh[nt]);
                    }
            }
            __syncthreads();
        }
        #pragma unroll
        for (int mt = 0; mt < 4; mt++)
            #pragma unroll
            for (int half = 0; half < 2; half++){
                const int r = wm + mt*16 + lr + half*8;
                #pragma unroll
                for (int nt = 0; nt < 4; nt++){
                    const int c0 = wnp + nt*8 + 2*lc;
                    float v0 = (c0   <= r) ? acc[mt][nt][half*2+0] : 0.f;
                    float v1 = (c0+1 <= r) ? acc[mt][nt][half*2+1] : 0.f;
                    *(float2*)&Ps[r*LDP + c0] = make_float2(v0, v1);
                }
            }
    }
    __syncthreads();

    // ------- phase 2: out = ([P|qp] @ [v;Sp]) / den, den fused in staging -------
    {
        float acc[4][2][4];
        #pragma unroll
        for (int i = 0; i < 4; i++)
            #pragma unroll
            for (int j = 0; j < 2; j++)
                #pragma unroll
                for (int t = 0; t < 4; t++) acc[i][j][t] = 0.f;

        const int bt = tid >> 4, bd0 = (tid & 15) * 4;
        float denp = 0.f;

        for (int kit = 0; kit < 16; kit++){
            const int j0 = kit * 16;
            #pragma unroll
            for (int q4 = 0; q4 < 2; q4++){
                float4 a;
                if (j0 < 128) a = *(const float4*)&Ps[rrow*LDP + j0 + kg + q4*4];
                else          a = *(const float4*)&g_qp[(qbase + rrow)*MMF + (j0 - 128) + kg + q4*4];
                float vals[4] = {a.x, a.y, a.z, a.w};
                if (j0 < 128){
                    denp += vals[0] + vals[1] + vals[2] + vals[3];
                } else {
                    float4 zpv = *(const float4*)&g_zp[sbase + (j0 - 128) + kg + q4*4];
                    denp += vals[0]*zpv.x + vals[1]*zpv.y + vals[2]*zpv.z + vals[3]*zpv.w;
                }
                #pragma unroll
                for (int i = 0; i < 4; i++){
                    unsigned hi, lo; tfsplit(vals[i], hi, lo);
                    Ah[(kg + q4*4 + i)*LDA + rrow] = hi;
                    Al[(kg + q4*4 + i)*LDA + rrow] = lo;
                }
            }
            {
                float4 hv;
                if (j0 < 128) hv = *(const float4*)&g_v[((size_t)(b*SS + c*128 + j0 + bt))*EE + h*DHH + bd0];
                else          hv = *(const float4*)&g_Sp[(sbase + (j0 - 128) + bt)*DHH + bd0];
                float vals[4] = {hv.x, hv.y, hv.z, hv.w};
                #pragma unroll
                for (int i = 0; i < 4; i++){
                    unsigned hi, lo; tfsplit(vals[i], hi, lo);
                    Bh[bt*KVLDB + bd0 + i] = hi;
                    Bl[bt*KVLDB + bd0 + i] = lo;
                }
            }
            __syncthreads();
            #pragma unroll
            for (int ks = 0; ks < 16; ks += 8){
                unsigned afh[4][4], afl[4][4], bfh[2][2], bfl[2][2];
                #pragma unroll
                for (int mt = 0; mt < 4; mt++){
                    const int base = (ks + lc)*LDA + wm + mt*16 + lr;
                    afh[mt][0] = Ah[base];         afl[mt][0] = Al[base];
                    afh[mt][1] = Ah[base + 8];     afl[mt][1] = Al[base + 8];
                    afh[mt][2] = Ah[base + 4*LDA]; afl[mt][2] = Al[base + 4*LDA];
                    afh[mt][3] = Ah[base + 4*LDA + 8]; afl[mt][3] = Al[base + 4*LDA + 8];
                }
                #pragma unroll
                for (int nt = 0; nt < 2; nt++){
                    const int base = (ks + lc)*KVLDB + wno + nt*8 + lr;
                    bfh[nt][0] = Bh[base];           bfl[nt][0] = Bl[base];
                    bfh[nt][1] = Bh[base + 4*KVLDB]; bfl[nt][1] = Bl[base + 4*KVLDB];
                }
                #pragma unroll
                for (int mt = 0; mt < 4; mt++)
                    #pragma unroll
                    for (int nt = 0; nt < 2; nt++){
                        MMA_TF32(acc[mt][nt], afh[mt], bfh[nt]);
                        MMA_TF32(acc[mt][nt], afh[mt], bfl[nt]);
                        MMA_TF32(acc[mt][nt], afl[mt], bfh[nt]);
                    }
            }
            __syncthreads();
        }
        denp += __shfl_xor_sync(~0u, denp, 1);
        if ((tid & 1) == 0) densh[rrow] = denp;
        __syncthreads();

        #pragma unroll
        for (int mt = 0; mt < 4; mt++)
            #pragma unroll
            for (int half = 0; half < 2; half++){
                const int r = wm + mt*16 + lr + half*8;
                const float dinv = 1.f / (densh[r] + DEPS);
                #pragma unroll
                for (int nt = 0; nt < 2; nt++){
                    const int d0 = wno + nt*8 + 2*lc;
                    *(float2*)&g_o[((size_t)(b*SS + c*128 + r))*EE + h*DHH + d0] =
                        make_float2(acc[mt][nt][half*2+0]*dinv, acc[mt][nt][half*2+1]*dinv);
                }
            }
    }
}

// ---------------- head projection ----------------
__global__ __launch_bounds__(64) void head_kernel(const float* __restrict__ hw, float* __restrict__ out)
{
    __shared__ float xs[EE];
    const int r = blockIdx.x, t = threadIdx.x;
    ((float4*)xs)[t]      = ((const float4*)(g_x + (size_t)r*EE))[t];
    ((float4*)xs)[t + 64] = ((const float4*)(g_x + (size_t)r*EE))[t + 64];
    __syncthreads();
    if (t < NVOC){
        float acc = 0.f;
        #pragma unroll 8
        for (int k = 0; k < EE; k++) acc += xs[k] * hw[k*NVOC + t];
        out[(size_t)r*NVOC + t] = acc;
    }
}

// ---------------- host launch ----------------
extern "C" void kernel_launch(void* const* d_in, const int* in_sizes, int n_in,
                              void* d_out, int out_size)
{
    (void)in_sizes; (void)n_in; (void)out_size;
    const int*   value = (const int*)  d_in[0];
    const int*   depth = (const int*)  d_in[1];
    const int*   pos   = (const int*)  d_in[2];
    const float* proj  = (const float*)d_in[3];
    const float* sos   = (const float*)d_in[4];
    const float* tok   = (const float*)d_in[5];
    const float* dep   = (const float*)d_in[6];
    const float* spa   = (const float*)d_in[7];
    const float* ln1w  = (const float*)d_in[8];
    const float* ln1b  = (const float*)d_in[9];
    const float* Wq    = (const float*)d_in[10];
    const float* bq    = (const float*)d_in[11];
    const float* Wk    = (const float*)d_in[12];
    const float* bk    = (const float*)d_in[13];
    const float* Wv    = (const float*)d_in[14];
    const float* bv    = (const float*)d_in[15];
    const float* Wo    = (const float*)d_in[16];
    const float* bo    = (const float*)d_in[17];
    const float* ln2w  = (const float*)d_in[18];
    const float* ln2b  = (const float*)d_in[19];
    const float* W1    = (const float*)d_in[20];
    const float* b1    = (const float*)d_in[21];
    const float* W2    = (const float*)d_in[22];
    const float* b2    = (const float*)d_in[23];
    const float* hw    = (const float*)d_in[24];

    float *px, *pq, *pk, *pv, *po, *pff;
    cudaGetSymbolAddress((void**)&px,  g_x);
    cudaGetSymbolAddress((void**)&pq,  g_q);
    cudaGetSymbolAddress((void**)&pk,  g_k);
    cudaGetSymbolAddress((void**)&pv,  g_v);
    cudaGetSymbolAddress((void**)&po,  g_o);
    cudaGetSymbolAddress((void**)&pff, g_ff);

    cudaFuncSetAttribute(po_kernel, cudaFuncAttributeMaxDynamicSharedMemorySize, PO_SMEM_BYTES);

    embed_kernel<<<(BSR*EE + 255)/256, 256>>>(value, depth, pos, sos, tok, dep, spa);
    prep_proj_kernel<<<(LL*DHH*MMF + 255)/256, 256>>>(proj);

    dim3 g512(4, 32);
    dim3 g2048(16, 32);
    dim3 gqkv(4, 32, 3);
    dim3 gfeat(NCH, BHH, 2);
    dim3 gchunk(NCH, BHH);
    dim3 gprefix(8, BHH);

    for (int l = 0; l < LL; l++){
        ln_stats_kernel<<<BSR, 128>>>(px);
        qkv_kernel<<<gqkv, 256>>>(px,
            Wq + (size_t)l*EE*EE, Wk + (size_t)l*EE*EE, Wv + (size_t)l*EE*EE,
            bq + l*EE, bk + l*EE, bv + l*EE,
            ln1w + l*EE, ln1b + l*EE,
            pq, pk, pv);

        feat_kernel<<<gfeat, 256>>>(l);
        kvz_kernel<<<gchunk, 256>>>(l);
        chunk_prefix_kernel<<<gprefix, 1024>>>();
        po_kernel<<<gchunk, 256, PO_SMEM_BYTES>>>();

        tgemm_kernel<<<g512, 256>>>(po, Wo + (size_t)l*EE*EE, bo + l*EE, px,
                                    nullptr, nullptr, px, EE, EE, 0);
        ln_stats_kernel<<<BSR, 128>>>(px);
        tgemm_kernel<<<g2048, 256>>>(px, W1 + (size_t)l*EE*FFD, b1 + l*FFD, nullptr,
                                     ln2w + l*EE, ln2b + l*EE, pff, FFD, EE, 1);
        tgemm_kernel<<<g512, 256>>>(pff, W2 + (size_t)l*FFD*EE, b2 + l*EE, px,
                                    nullptr, nullptr, px, EE, FFD, 0);
    }

    head_kernel<<<BSR, 64>>>(hw, (float*)d_out);
}

// round 9
// speedup vs baseline: 1.0474x; 1.0474x over previous
#include <cuda_runtime.h>
#include <cuda_bf16.h>
#include <math.h>

// ---------------- problem constants ----------------
#define BB   2
#define SS   2048
#define EE   512
#define HH   8
#define LL   4
#define DHH  64
#define MMF  128
#define AAX  3
#define NVOC 17
#define BHH  (BB*HH)      // 16
#define BSR  (BB*SS)      // 4096
#define NCH  (SS/128)     // 16
#define FFD  (4*EE)       // 2048

#define DNQ   0.3535533905932738f
#define RATIO 0.08838834764831845f
#define KEPS  1e-4f
#define DEPS  1e-6f

// ---------------- scratch ----------------
__device__ float g_x [BSR*EE];
__device__ float g_h [BSR*EE];
__device__ float g_q [BSR*EE];
__device__ float g_k [BSR*EE];
__device__ float g_v [BSR*EE];
__device__ float g_o [BSR*EE];
__device__ float g_ff[BSR*FFD];
__device__ float g_qp[BHH*SS*MMF];
__device__ float g_kp[BHH*SS*MMF];
__device__ unsigned g_kmaxv[LL];
__device__ float g_Sc[BHH*NCH*MMF*DHH];
__device__ float g_Sp[BHH*NCH*MMF*DHH];
__device__ float g_zc[BHH*NCH*MMF];
__device__ float g_zp[BHH*NCH*MMF];
__device__ unsigned g_projh[LL*DHH*MMF];   // transposed [l][k][m], tf32 hi
__device__ unsigned g_projl[LL*DHH*MMF];   // transposed [l][k][m], tf32 lo

// ---------------- helpers ----------------
__device__ __forceinline__ unsigned f_enc(float f){
    unsigned u = __float_as_uint(f);
    return (u & 0x80000000u) ? ~u : (u | 0x80000000u);
}
__device__ __forceinline__ float f_dec(unsigned u){
    return (u & 0x80000000u) ? __uint_as_float(u & 0x7fffffffu) : __uint_as_float(~u);
}
__device__ __forceinline__ unsigned f2tf(float x){
    unsigned r; asm("cvt.rna.tf32.f32 %0, %1;" : "=r"(r) : "f"(x)); return r;
}

#define MMA_TF32(c, a, b) asm volatile( \
  "mma.sync.aligned.m16n8k8.row.col.f32.tf32.tf32.f32 " \
  "{%0,%1,%2,%3}, {%4,%5,%6,%7}, {%8,%9}, {%0,%1,%2,%3};" \
  : "+f"(c[0]),"+f"(c[1]),"+f"(c[2]),"+f"(c[3]) \
  : "r"(a[0]),"r"(a[1]),"r"(a[2]),"r"(a[3]), "r"(b[0]),"r"(b[1]))

__device__ __forceinline__ void tfsplit(float x, unsigned& hi, unsigned& lo){
    hi = f2tf(x);
    lo = f2tf(x - __uint_as_float(hi));
}

// ---------------- embedding (+ per-layer kmax reset) ----------------
__global__ void embed_kernel(const int* __restrict__ value, const int* __restrict__ depth,
                             const int* __restrict__ pos,   const float* __restrict__ sos,
                             const float* __restrict__ tok, const float* __restrict__ dep,
                             const float* __restrict__ spa)
{
    if (blockIdx.x == 0 && threadIdx.x < LL) g_kmaxv[threadIdx.x] = 0u;
    int i = blockIdx.x * 256 + threadIdx.x;
    if (i >= BSR*EE) return;
    int e = i & (EE-1);
    int r = i >> 9;
    int b = r / SS, s = r - b*SS;
    float val;
    if (s == 0) val = sos[e];
    else {
        int p = b*SS + s - 1;
        val = tok[value[p]*EE + e] + dep[depth[p]*EE + e];
        #pragma unroll
        for (int a = 0; a < AAX; a++)
            val += spa[(size_t)a*65*EE + pos[p*AAX + a]*EE + e];
    }
    g_x[i] = val;
}

// ---------------- proj precompute: transposed hi/lo splits ----------------
__global__ void prep_proj_kernel(const float* __restrict__ proj)
{
    int i = blockIdx.x * 256 + threadIdx.x;      // i over LL*DHH*MMF
    if (i >= LL*DHH*MMF) return;
    int l = i / (DHH*MMF);
    int rem = i - l*(DHH*MMF);
    int k = rem >> 7;            // 0..63
    int m = rem & 127;           // 0..127
    float v = proj[(size_t)l*MMF*DHH + m*DHH + k];
    unsigned hi, lo; tfsplit(v, hi, lo);
    g_projh[i] = hi;
    g_projl[i] = lo;
}

// ---------------- layernorm ----------------
__global__ __launch_bounds__(128) void ln_kernel(const float* __restrict__ in, float* __restrict__ out,
                                                 const float* __restrict__ w, const float* __restrict__ bia)
{
    int r = blockIdx.x, t = threadIdx.x;
    const float4 v = ((const float4*)(in + (size_t)r*EE))[t];
    float s  = v.x + v.y + v.z + v.w;
    float sq = v.x*v.x + v.y*v.y + v.z*v.z + v.w*v.w;
    #pragma unroll
    for (int o = 16; o; o >>= 1){ s += __shfl_xor_sync(~0u, s, o); sq += __shfl_xor_sync(~0u, sq, o); }
    __shared__ float sh[8];
    if ((t & 31) == 0){ sh[t>>5] = s; sh[4 + (t>>5)] = sq; }
    __syncthreads();
    s  = sh[0]+sh[1]+sh[2]+sh[3];
    sq = sh[4]+sh[5]+sh[6]+sh[7];
    float mu  = s * (1.f/EE);
    float var = sq * (1.f/EE) - mu*mu;
    float rs  = rsqrtf(var + 1e-5f);
    float4 wv = ((const float4*)w)[t], bv = ((const float4*)bia)[t];
    float4 o4;
    o4.x = (v.x-mu)*rs*wv.x + bv.x;
    o4.y = (v.y-mu)*rs*wv.y + bv.y;
    o4.z = (v.z-mu)*rs*wv.z + bv.z;
    o4.w = (v.w-mu)*rs*wv.w + bv.w;
    ((float4*)(out + (size_t)r*EE))[t] = o4;
}

// ---------------- tf32 GEMM (weights) — R4 layout, vectorized B staging ----------------
#define BKK 16
#define LDA 136
#define LDB 136

__device__ __forceinline__ void gemm_body(
    const float* __restrict__ Am, const float* __restrict__ Bm,
    const float* __restrict__ bias, const float* __restrict__ resid,
    float* __restrict__ C, int N, int K, int act,
    unsigned* As, unsigned* Bs)
{
    const int tid = threadIdx.x;
    const int bm = blockIdx.y * 128, bn = blockIdx.x * 128;
    const int w = tid >> 5, lane = tid & 31;
    const int wm = (w & 1) * 64, wn = (w >> 1) * 32;
    const int lr = lane >> 2, lc = lane & 3;

    float acc[4][4][4];
    #pragma unroll
    for (int i = 0; i < 4; i++)
        #pragma unroll
        for (int j = 0; j < 4; j++)
            #pragma unroll
            for (int t = 0; t < 4; t++) acc[i][j][t] = 0.f;

    const int f0 = tid, f1 = tid + 256;
    const int ar0 = f0 >> 2, ak0 = (f0 & 3) << 2;
    const int ar1 = f1 >> 2, ak1 = (f1 & 3) << 2;
    const int br0 = f0 >> 5, bc0 = (f0 & 31) << 2;
    const int br1 = f1 >> 5, bc1 = (f1 & 31) << 2;

    float4 a4[2], b4[2];
    const int nk = K / BKK;

    a4[0] = *(const float4*)&Am[(size_t)(bm + ar0)*K + ak0];
    a4[1] = *(const float4*)&Am[(size_t)(bm + ar1)*K + ak1];
    b4[0] = *(const float4*)&Bm[(size_t)br0*N + bn + bc0];
    b4[1] = *(const float4*)&Bm[(size_t)br1*N + bn + bc1];
    {
        unsigned* Ab = As; unsigned* Bb = Bs;
        Ab[(ak0+0)*LDA + ar0] = f2tf(a4[0].x); Ab[(ak0+1)*LDA + ar0] = f2tf(a4[0].y);
        Ab[(ak0+2)*LDA + ar0] = f2tf(a4[0].z); Ab[(ak0+3)*LDA + ar0] = f2tf(a4[0].w);
        Ab[(ak1+0)*LDA + ar1] = f2tf(a4[1].x); Ab[(ak1+1)*LDA + ar1] = f2tf(a4[1].y);
        Ab[(ak1+2)*LDA + ar1] = f2tf(a4[1].z); Ab[(ak1+3)*LDA + ar1] = f2tf(a4[1].w);
        uint4 bv0 = make_uint4(f2tf(b4[0].x), f2tf(b4[0].y), f2tf(b4[0].z), f2tf(b4[0].w));
        uint4 bv1 = make_uint4(f2tf(b4[1].x), f2tf(b4[1].y), f2tf(b4[1].z), f2tf(b4[1].w));
        *(uint4*)&Bb[br0*LDB + bc0] = bv0;
        *(uint4*)&Bb[br1*LDB + bc1] = bv1;
    }
    __syncthreads();

    for (int it = 0; it < nk; it++){
        const int cur = it & 1;
        if (it + 1 < nk){
            const int k0 = (it + 1) * BKK;
            a4[0] = *(const float4*)&Am[(size_t)(bm + ar0)*K + k0 + ak0];
            a4[1] = *(const float4*)&Am[(size_t)(bm + ar1)*K + k0 + ak1];
            b4[0] = *(const float4*)&Bm[(size_t)(k0 + br0)*N + bn + bc0];
            b4[1] = *(const float4*)&Bm[(size_t)(k0 + br1)*N + bn + bc1];
        }
        {
            const unsigned* Ab = As + cur * (BKK * LDA);
            const unsigned* Bb = Bs + cur * (BKK * LDB);
            #pragma unroll
            for (int ks = 0; ks < BKK; ks += 8){
                unsigned af[4][4], bf[4][2];
                #pragma unroll
                for (int mt = 0; mt < 4; mt++){
                    const int base = (ks + lc)*LDA + wm + mt*16 + lr;
                    af[mt][0] = Ab[base];
                    af[mt][1] = Ab[base + 8];
                    af[mt][2] = Ab[base + 4*LDA];
                    af[mt][3] = Ab[base + 4*LDA + 8];
                }
                #pragma unroll
                for (int nt = 0; nt < 4; nt++){
                    const int base = (ks + lc)*LDB + wn + nt*8 + lr;
                    bf[nt][0] = Bb[base];
                    bf[nt][1] = Bb[base + 4*LDB];
                }
                #pragma unroll
                for (int mt = 0; mt < 4; mt++)
                    #pragma unroll
                    for (int nt = 0; nt < 4; nt++)
                        MMA_TF32(acc[mt][nt], af[mt], bf[nt]);
            }
        }
        if (it + 1 < nk){
            unsigned* Ab = As + (cur ^ 1) * (BKK * LDA);
            unsigned* Bb = Bs + (cur ^ 1) * (BKK * LDB);
            Ab[(ak0+0)*LDA + ar0] = f2tf(a4[0].x); Ab[(ak0+1)*LDA + ar0] = f2tf(a4[0].y);
            Ab[(ak0+2)*LDA + ar0] = f2tf(a4[0].z); Ab[(ak0+3)*LDA + ar0] = f2tf(a4[0].w);
            Ab[(ak1+0)*LDA + ar1] = f2tf(a4[1].x); Ab[(ak1+1)*LDA + ar1] = f2tf(a4[1].y);
            Ab[(ak1+2)*LDA + ar1] = f2tf(a4[1].z); Ab[(ak1+3)*LDA + ar1] = f2tf(a4[1].w);
            uint4 bv0 = make_uint4(f2tf(b4[0].x), f2tf(b4[0].y), f2tf(b4[0].z), f2tf(b4[0].w));
            uint4 bv1 = make_uint4(f2tf(b4[1].x), f2tf(b4[1].y), f2tf(b4[1].z), f2tf(b4[1].w));
            *(uint4*)&Bb[br0*LDB + bc0] = bv0;
            *(uint4*)&Bb[br1*LDB + bc1] = bv1;
        }
        __syncthreads();
    }

    #pragma unroll
    for (int mt = 0; mt < 4; mt++){
        const int r0 = bm + wm + mt*16 + lr;
        #pragma unroll
        for (int nt = 0; nt < 4; nt++){
            const int c0 = bn + wn + nt*8 + 2*lc;
            const float bx = bias[c0], by = bias[c0+1];
            #pragma unroll
            for (int half = 0; half < 2; half++){
                const int r = r0 + half*8;
                float v0 = acc[mt][nt][half*2+0] + bx;
                float v1 = acc[mt][nt][half*2+1] + by;
                if (act){
                    v0 = 0.5f*v0*(1.f + erff(v0*0.70710678118654752f));
                    v1 = 0.5f*v1*(1.f + erff(v1*0.70710678118654752f));
                }
                if (resid){
                    v0 += resid[(size_t)r*N + c0];
                    v1 += resid[(size_t)r*N + c0+1];
                }
                *(float2*)&C[(size_t)r*N + c0] = make_float2(v0, v1);
            }
        }
    }
}

__global__ __launch_bounds__(256, 2) void tgemm_kernel(
    const float* __restrict__ A, const float* __restrict__ Bm,
    const float* __restrict__ bias, const float* __restrict__ resid,
    float* __restrict__ C, int N, int K, int act)
{
    __shared__ __align__(16) unsigned As[2*BKK*LDA];
    __shared__ __align__(16) unsigned Bs[2*BKK*LDB];
    gemm_body(A, Bm, bias, resid, C, N, K, act, As, Bs);
}

__global__ __launch_bounds__(256, 2) void qkv_kernel(
    const float* __restrict__ A,
    const float* __restrict__ Wq, const float* __restrict__ Wk, const float* __restrict__ Wv,
    const float* __restrict__ bq, const float* __restrict__ bk, const float* __restrict__ bv,
    float* __restrict__ oq, float* __restrict__ ok, float* __restrict__ ov)
{
    __shared__ __align__(16) unsigned As[2*BKK*LDA];
    __shared__ __align__(16) unsigned Bs[2*BKK*LDB];
    const int z = blockIdx.z;
    const float* Bm  = (z == 0) ? Wq : (z == 1) ? Wk : Wv;
    const float* bi  = (z == 0) ? bq : (z == 1) ? bk : bv;
    float*       Cm  = (z == 0) ? oq : (z == 1) ? ok : ov;
    gemm_body(A, Bm, bi, nullptr, Cm, EE, EE, 0, As, Bs);
}

// ================= FAVOR features via 3xTF32 MMA (precomputed proj splits) ===========
__global__ __launch_bounds__(256) void feat_kernel(int l)
{
    __shared__ unsigned Ah[16*LDA], Al[16*LDA], Bh[16*LDB], Bl[16*LDB];
    __shared__ float diag[128];
    __shared__ unsigned rmax[128];
    __shared__ unsigned bmax;
    const int tid = threadIdx.x;
    const int c = blockIdx.x, bh = blockIdx.y;
    const int isq = (blockIdx.z == 0);
    const int b = bh / HH, h = bh % HH;
    const float* src = isq ? g_q : g_k;
    const unsigned* prjh = g_projh + (size_t)l*DHH*MMF;
    const unsigned* prjl = g_projl + (size_t)l*DHH*MMF;
    const int w = tid >> 5, lane = tid & 31;
    const int wm = (w & 1) * 64, wn = (w >> 1) * 32;
    const int lr = lane >> 2, lc = lane & 3;

    if (tid < 128) rmax[tid] = 0u;
    if (tid == 0) bmax = 0u;

    float acc[4][4][4];
    #pragma unroll
    for (int i = 0; i < 4; i++)
        #pragma unroll
        for (int j = 0; j < 4; j++)
            #pragma unroll
            for (int t = 0; t < 4; t++) acc[i][j][t] = 0.f;

    const int rrow = tid >> 1, kg = (tid & 1) * 8;
    const int bk = tid >> 4, bm0 = (tid & 15) * 8;     // B staging (transposed layout)
    float sq = 0.f;

    for (int kit = 0; kit < 4; kit++){
        const int k0 = kit * 16;
        // A: x rows (scaled) — staged k-major with tfsplit
        #pragma unroll
        for (int q4 = 0; q4 < 2; q4++){
            float4 a = *(const float4*)&src[((size_t)(b*SS + c*128 + rrow))*EE + h*DHH + k0 + kg + q4*4];
            float vals[4] = {a.x*DNQ, a.y*DNQ, a.z*DNQ, a.w*DNQ};
            #pragma unroll
            for (int i = 0; i < 4; i++){
                sq += vals[i]*vals[i];
                unsigned hi, lo; tfsplit(vals[i], hi, lo);
                Ah[(kg + q4*4 + i)*LDA + rrow] = hi;
                Al[(kg + q4*4 + i)*LDA + rrow] = lo;
            }
        }
        // B: precomputed transposed hi/lo proj — vector copies
        {
            const size_t pb = (size_t)(k0 + bk)*MMF + bm0;
            uint4 h0 = *(const uint4*)&prjh[pb];
            uint4 h1 = *(const uint4*)&prjh[pb + 4];
            uint4 l0 = *(const uint4*)&prjl[pb];
            uint4 l1 = *(const uint4*)&prjl[pb + 4];
            *(uint4*)&Bh[bk*LDB + bm0]     = h0;
            *(uint4*)&Bh[bk*LDB + bm0 + 4] = h1;
            *(uint4*)&Bl[bk*LDB + bm0]     = l0;
            *(uint4*)&Bl[bk*LDB + bm0 + 4] = l1;
        }
        __syncthreads();
        #pragma unroll
        for (int ks = 0; ks < 16; ks += 8){
            unsigned afh[4][4], afl[4][4], bfh[4][2], bfl[4][2];
            #pragma unroll
            for (int mt = 0; mt < 4; mt++){
                const int base = (ks + lc)*LDA + wm + mt*16 + lr;
                afh[mt][0] = Ah[base];        afl[mt][0] = Al[base];
                afh[mt][1] = Ah[base + 8];    afl[mt][1] = Al[base + 8];
                afh[mt][2] = Ah[base + 4*LDA];afl[mt][2] = Al[base + 4*LDA];
                afh[mt][3] = Ah[base + 4*LDA + 8]; afl[mt][3] = Al[base + 4*LDA + 8];
            }
            #pragma unroll
            for (int nt = 0; nt < 4; nt++){
                const int base = (ks + lc)*LDB + wn + nt*8 + lr;
                bfh[nt][0] = Bh[base];         bfl[nt][0] = Bl[base];
                bfh[nt][1] = Bh[base + 4*LDB]; bfl[nt][1] = Bl[base + 4*LDB];
            }
            #pragma unroll
            for (int mt = 0; mt < 4; mt++)
                #pragma unroll
                for (int nt = 0; nt < 4; nt++){
                    MMA_TF32(acc[mt][nt], afh[mt], bfh[nt]);
                    MMA_TF32(acc[mt][nt], afh[mt], bfl[nt]);
                    MMA_TF32(acc[mt][nt], afl[mt], bfh[nt]);
                }
        }
        __syncthreads();
    }
    {
        float other = __shfl_xor_sync(~0u, sq, 1);
        if ((tid & 1) == 0) diag[rrow] = 0.5f * (sq + other);
    }
    if (isq){
        #pragma unroll
        for (int mt = 0; mt < 4; mt++)
            #pragma unroll
            for (int half = 0; half < 2; half++){
                const int r = wm + mt*16 + lr + half*8;
                float m = -3.4e38f;
                #pragma unroll
                for (int nt = 0; nt < 4; nt++){
                    m = fmaxf(m, acc[mt][nt][half*2+0]);
                    m = fmaxf(m, acc[mt][nt][half*2+1]);
                }
                atomicMax(&rmax[r], f_enc(m));
            }
    } else {
        float m = -3.4e38f;
        #pragma unroll
        for (int mt = 0; mt < 4; mt++)
            #pragma unroll
            for (int nt = 0; nt < 4; nt++)
                #pragma unroll
                for (int t = 0; t < 4; t++) m = fmaxf(m, acc[mt][nt][t]);
        #pragma unroll
        for (int o = 16; o; o >>= 1) m = fmaxf(m, __shfl_xor_sync(~0u, m, o));
        if (lane == 0) atomicMax(&bmax, f_enc(m));
    }
    __syncthreads();

    const size_t qbase = (size_t)bh*SS + c*128;
    if (isq){
        #pragma unroll
        for (int mt = 0; mt < 4; mt++)
            #pragma unroll
            for (int half = 0; half < 2; half++){
                const int r = wm + mt*16 + lr + half*8;
                const float dg = diag[r], mx = f_dec(rmax[r]);
                #pragma unroll
                for (int nt = 0; nt < 4; nt++){
                    const int c0 = wn + nt*8 + 2*lc;
                    float v0 = RATIO*(expf(acc[mt][nt][half*2+0] - dg - mx) + KEPS);
                    float v1 = RATIO*(expf(acc[mt][nt][half*2+1] - dg - mx) + KEPS);
                    *(float2*)&g_qp[(qbase + r)*MMF + c0] = make_float2(v0, v1);
                }
            }
    } else {
        if (tid == 0) atomicMax(&g_kmaxv[l], bmax);
        #pragma unroll
        for (int mt = 0; mt < 4; mt++)
            #pragma unroll
            for (int half = 0; half < 2; half++){
                const int r = wm + mt*16 + lr + half*8;
                const float dg = diag[r];
                #pragma unroll
                for (int nt = 0; nt < 4; nt++){
                    const int c0 = wn + nt*8 + 2*lc;
                    float v0 = acc[mt][nt][half*2+0] - dg;
                    float v1 = acc[mt][nt][half*2+1] - dg;
                    *(float2*)&g_kp[(qbase + r)*MMF + c0] = make_float2(v0, v1);
                }
            }
    }
}

// ========== fused: kp exp-transform + writeback + zc + Sc (3xTF32 MMA) ==========
#define KVLDB 72
__global__ __launch_bounds__(256, 2) void kvz_kernel(int l)
{
    __shared__ unsigned Ah[16*LDA], Al[16*LDA], Bh[16*KVLDB], Bl[16*KVLDB];
    __shared__ float zcs[128];
    const int c = blockIdx.x, bh = blockIdx.y;
    const int b = bh / HH, h = bh % HH;
    const int tid = threadIdx.x;
    const int w = tid >> 5, lane = tid & 31;
    const int wm = (w & 1) * 64, wn = (w >> 1) * 16;
    const int lr = lane >> 2, lc = lane & 3;
    const size_t qbase = (size_t)bh*SS + c*128;
    const float gm = f_dec(g_kmaxv[l]);

    if (tid < 128) zcs[tid] = 0.f;

    float acc[4][2][4];
    #pragma unroll
    for (int i = 0; i < 4; i++)
        #pragma unroll
        for (int j = 0; j < 2; j++)
            #pragma unroll
            for (int t = 0; t < 4; t++) acc[i][j][t] = 0.f;

    const int at = tid >> 4, am0 = (tid & 15) * 8;
    const int bt = tid >> 4, bd0 = (tid & 15) * 4;
    float zcp[8];
    #pragma unroll
    for (int i = 0; i < 8; i++) zcp[i] = 0.f;

    for (int kit = 0; kit < 8; kit++){
        const int t0 = kit * 16;
        #pragma unroll
        for (int q4 = 0; q4 < 2; q4++){
            size_t off = (qbase + t0 + at)*MMF + am0 + q4*4;
            float4 a = *(const float4*)&g_kp[off];
            float vals[4];
            vals[0] = RATIO*(expf(a.x - gm) + KEPS);
            vals[1] = RATIO*(expf(a.y - gm) + KEPS);
            vals[2] = RATIO*(expf(a.z - gm) + KEPS);
            vals[3] = RATIO*(expf(a.w - gm) + KEPS);
            *(float4*)&g_kp[off] = make_float4(vals[0], vals[1], vals[2], vals[3]);
            #pragma unroll
            for (int i = 0; i < 4; i++){
                zcp[q4*4 + i] += vals[i];
                unsigned hi, lo; tfsplit(vals[i], hi, lo);
                Ah[at*LDA + am0 + q4*4 + i] = hi;
                Al[at*LDA + am0 + q4*4 + i] = lo;
            }
        }
        {
            float4 vv = *(const float4*)&g_v[((size_t)(b*SS + c*128 + t0 + bt))*EE + h*DHH + bd0];
            float vals[4] = {vv.x, vv.y, vv.z, vv.w};
            #pragma unroll
            for (int i = 0; i < 4; i++){
                unsigned hi, lo; tfsplit(vals[i], hi, lo);
                Bh[bt*KVLDB + bd0 + i] = hi;
                Bl[bt*KVLDB + bd0 + i] = lo;
            }
        }
        __syncthreads();
        #pragma unroll
        for (int ks = 0; ks < 16; ks += 8){
            unsigned afh[4][4], afl[4][4], bfh[2][2], bfl[2][2];
            #pragma unroll
            for (int mt = 0; mt < 4; mt++){
                const int base = (ks + lc)*LDA + wm + mt*16 + lr;
                afh[mt][0] = Ah[base];         afl[mt][0] = Al[base];
                afh[mt][1] = Ah[base + 8];     afl[mt][1] = Al[base + 8];
                afh[mt][2] = Ah[base + 4*LDA]; afl[mt][2] = Al[base + 4*LDA];
                afh[mt][3] = Ah[base + 4*LDA + 8]; afl[mt][3] = Al[base + 4*LDA + 8];
            }
            #pragma unroll
            for (int nt = 0; nt < 2; nt++){
                const int base = (ks + lc)*KVLDB + wn + nt*8 + lr;
                bfh[nt][0] = Bh[base];           bfl[nt][0] = Bl[base];
                bfh[nt][1] = Bh[base + 4*KVLDB]; bfl[nt][1] = Bl[base + 4*KVLDB];
            }
            #pragma unroll
            for (int mt = 0; mt < 4; mt++)
                #pragma unroll
                for (int nt = 0; nt < 2; nt++){
                    MMA_TF32(acc[mt][nt], afh[mt], bfh[nt]);
                    MMA_TF32(acc[mt][nt], afh[mt], bfl[nt]);
                    MMA_TF32(acc[mt][nt], afl[mt], bfh[nt]);
                }
        }
        __syncthreads();
    }
    #pragma unroll
    for (int i = 0; i < 8; i++) atomicAdd(&zcs[am0 + i], zcp[i]);
    __syncthreads();
    if (tid < 128) g_zc[(bh*NCH + c)*MMF + tid] = zcs[tid];

    const size_t base = ((size_t)(bh*NCH + c))*MMF;
    #pragma unroll
    for (int mt = 0; mt < 4; mt++)
        #pragma unroll
        for (int half = 0; half < 2; half++){
            const int m = wm + mt*16 + lr + half*8;
            #pragma unroll
            for (int nt = 0; nt < 2; nt++){
                const int d0 = wn + nt*8 + 2*lc;
                *(float2*)&g_Sc[(base + m)*DHH + d0] =
                    make_float2(acc[mt][nt][half*2+0], acc[mt][nt][half*2+1]);
            }
        }
}

// ---------------- parallel exclusive prefix over chunks ----------------
__global__ __launch_bounds__(1024) void chunk_prefix_kernel()
{
    const int bh = blockIdx.y;
    const int idx = blockIdx.x * 1024 + threadIdx.x;
    float run = 0.f;
    #pragma unroll
    for (int c = 0; c < NCH; c++){
        size_t off = ((size_t)(bh*NCH + c))*MMF*DHH + idx;
        float v = g_Sc[off];
        g_Sp[off] = run;
        run += v;
    }
    if (blockIdx.x == 0 && threadIdx.x < MMF){
        const int m = threadIdx.x;
        float rz = 0.f;
        #pragma unroll
        for (int c = 0; c < NCH; c++){
            int zb = (bh*NCH + c)*MMF + m;
            g_zp[zb] = rz;
            rz += g_zc[zb];
        }
    }
}

// ======= FUSED: P = mask(qp@kp^T) in smem, then out = ([P|qp]@[v;Sp])/den =======
#define LDP 132
#define PO_PS_WORDS (128*LDP)          // 16896
#define PO_AB_WORDS (16*LDA)           // 2176
#define PO_SMEM_BYTES ((PO_PS_WORDS + 4*PO_AB_WORDS + 128) * 4)   // 102912 B

__global__ __launch_bounds__(256) void po_kernel()
{
    extern __shared__ __align__(16) float po_smem[];
    float*    Ps    = po_smem;
    unsigned* Ah    = (unsigned*)(po_smem + PO_PS_WORDS);
    unsigned* Al    = Ah + PO_AB_WORDS;
    unsigned* Bh    = Al + PO_AB_WORDS;
    unsigned* Bl    = Bh + PO_AB_WORDS;
    float*    densh = (float*)(Bl + PO_AB_WORDS);

    const int c = blockIdx.x, bh = blockIdx.y;
    const int b = bh / HH, h = bh % HH;
    const int tid = threadIdx.x;
    const int w = tid >> 5, lane = tid & 31;
    const int wm = (w & 1) * 64;
    const int wnp = (w >> 1) * 32;
    const int wno = (w >> 1) * 16;
    const int lr = lane >> 2, lc = lane & 3;
    const size_t qbase = (size_t)bh*SS + c*128;
    const size_t sbase = ((size_t)(bh*NCH + c))*MMF;
    const int rrow = tid >> 1, kg = (tid & 1) * 8;

    // ---------------- phase 1: P = mask(qp @ kp^T) ----------------
    {
        float acc[4][4][4];
        #pragma unroll
        for (int i = 0; i < 4; i++)
            #pragma unroll
            for (int j = 0; j < 4; j++)
                #pragma unroll
                for (int t = 0; t < 4; t++) acc[i][j][t] = 0.f;

        for (int kit = 0; kit < 8; kit++){
            const int m0 = kit * 16;
            #pragma unroll
            for (int q4 = 0; q4 < 2; q4++){
                float4 a = *(const float4*)&g_qp[(qbase + rrow)*MMF + m0 + kg + q4*4];
                float va[4] = {a.x, a.y, a.z, a.w};
                float4 bk = *(const float4*)&g_kp[(qbase + rrow)*MMF + m0 + kg + q4*4];
                float vb[4] = {bk.x, bk.y, bk.z, bk.w};
                #pragma unroll
                for (int i = 0; i < 4; i++){
                    unsigned hi, lo;
                    tfsplit(va[i], hi, lo);
                    Ah[(kg + q4*4 + i)*LDA + rrow] = hi;
                    Al[(kg + q4*4 + i)*LDA + rrow] = lo;
                    tfsplit(vb[i], hi, lo);
                    Bh[(kg + q4*4 + i)*LDB + rrow] = hi;
                    Bl[(kg + q4*4 + i)*LDB + rrow] = lo;
                }
            }
            __syncthreads();
            #pragma unroll
            for (int ks = 0; ks < 16; ks += 8){
                unsigned afh[4][4], afl[4][4], bfh[4][2], bfl[4][2];
                #pragma unroll
                for (int mt = 0; mt < 4; mt++){
                    const int base = (ks + lc)*LDA + wm + mt*16 + lr;
                    afh[mt][0] = Ah[base];         afl[mt][0] = Al[base];
                    afh[mt][1] = Ah[base + 8];     afl[mt][1] = Al[base + 8];
                    afh[mt][2] = Ah[base + 4*LDA]; afl[mt][2] = Al[base + 4*LDA];
                    afh[mt][3] = Ah[base + 4*LDA + 8]; afl[mt][3] = Al[base + 4*LDA + 8];
                }
                #pragma unroll
                for (int nt = 0; nt < 4; nt++){
                    const int base = (ks + lc)*LDB + wnp + nt*8 + lr;
                    bfh[nt][0] = Bh[base];         bfl[nt][0] = Bl[base];
                    bfh[nt][1] = Bh[base + 4*LDB]; bfl[nt][1] = Bl[base + 4*LDB];
                }
                #pragma unroll
                for (int mt = 0; mt < 4; mt++)
                    #pragma unroll
                    for (int nt = 0; nt < 4; nt++){
                        MMA_TF32(acc[mt][nt], afh[mt], bfh[nt]);
                        MMA_TF32(acc[mt][nt], afh[mt], bfl[nt]);
                        MMA_TF32(acc[mt][nt], afl[mt], bfh[nt]);
                    }
            }
            __syncthreads();
        }
        #pragma unroll
        for (int mt = 0; mt < 4; mt++)
            #pragma unroll
            for (int half = 0; half < 2; half++){
                const int r = wm + mt*16 + lr + half*8;
                #pragma unroll
                for (int nt = 0; nt < 4; nt++){
                    const int c0 = wnp + nt*8 + 2*lc;
                    float v0 = (c0   <= r) ? acc[mt][nt][half*2+0] : 0.f;
                    float v1 = (c0+1 <= r) ? acc[mt][nt][half*2+1] : 0.f;
                    *(float2*)&Ps[r*LDP + c0] = make_float2(v0, v1);
                }
            }
    }
    __syncthreads();

    // ------- phase 2: out = ([P|qp] @ [v;Sp]) / den, den fused in staging -------
    {
        float acc[4][2][4];
        #pragma unroll
        for (int i = 0; i < 4; i++)
            #pragma unroll
            for (int j = 0; j < 2; j++)
                #pragma unroll
                for (int t = 0; t < 4; t++) acc[i][j][t] = 0.f;

        const int bt = tid >> 4, bd0 = (tid & 15) * 4;
        float denp = 0.f;

        for (int kit = 0; kit < 16; kit++){
            const int j0 = kit * 16;
            #pragma unroll
            for (int q4 = 0; q4 < 2; q4++){
                float4 a;
                if (j0 < 128) a = *(const float4*)&Ps[rrow*LDP + j0 + kg + q4*4];
                else          a = *(const float4*)&g_qp[(qbase + rrow)*MMF + (j0 - 128) + kg + q4*4];
                float vals[4] = {a.x, a.y, a.z, a.w};
                if (j0 < 128){
                    denp += vals[0] + vals[1] + vals[2] + vals[3];
                } else {
                    float4 zpv = *(const float4*)&g_zp[sbase + (j0 - 128) + kg + q4*4];
                    denp += vals[0]*zpv.x + vals[1]*zpv.y + vals[2]*zpv.z + vals[3]*zpv.w;
                }
                #pragma unroll
                for (int i = 0; i < 4; i++){
                    unsigned hi, lo; tfsplit(vals[i], hi, lo);
                    Ah[(kg + q4*4 + i)*LDA + rrow] = hi;
                    Al[(kg + q4*4 + i)*LDA + rrow] = lo;
                }
            }
            {
                float4 hv;
                if (j0 < 128) hv = *(const float4*)&g_v[((size_t)(b*SS + c*128 + j0 + bt))*EE + h*DHH + bd0];
                else          hv = *(const float4*)&g_Sp[(sbase + (j0 - 128) + bt)*DHH + bd0];
                float vals[4] = {hv.x, hv.y, hv.z, hv.w};
                #pragma unroll
                for (int i = 0; i < 4; i++){
                    unsigned hi, lo; tfsplit(vals[i], hi, lo);
                    Bh[bt*KVLDB + bd0 + i] = hi;
                    Bl[bt*KVLDB + bd0 + i] = lo;
                }
            }
            __syncthreads();
            #pragma unroll
            for (int ks = 0; ks < 16; ks += 8){
                unsigned afh[4][4], afl[4][4], bfh[2][2], bfl[2][2];
                #pragma unroll
                for (int mt = 0; mt < 4; mt++){
                    const int base = (ks + lc)*LDA + wm + mt*16 + lr;
                    afh[mt][0] = Ah[base];         afl[mt][0] = Al[base];
                    afh[mt][1] = Ah[base + 8];     afl[mt][1] = Al[base + 8];
                    afh[mt][2] = Ah[base + 4*LDA]; afl[mt][2] = Al[base + 4*LDA];
                    afh[mt][3] = Ah[base + 4*LDA + 8]; afl[mt][3] = Al[base + 4*LDA + 8];
                }
                #pragma unroll
                for (int nt = 0; nt < 2; nt++){
                    const int base = (ks + lc)*KVLDB + wno + nt*8 + lr;
                    bfh[nt][0] = Bh[base];           bfl[nt][0] = Bl[base];
                    bfh[nt][1] = Bh[base + 4*KVLDB]; bfl[nt][1] = Bl[base + 4*KVLDB];
                }
                #pragma unroll
                for (int mt = 0; mt < 4; mt++)
                    #pragma unroll
                    for (int nt = 0; nt < 2; nt++){
                        MMA_TF32(acc[mt][nt], afh[mt], bfh[nt]);
                        MMA_TF32(acc[mt][nt], afh[mt], bfl[nt]);
                        MMA_TF32(acc[mt][nt], afl[mt], bfh[nt]);
                    }
            }
            __syncthreads();
        }
        denp += __shfl_xor_sync(~0u, denp, 1);
        if ((tid & 1) == 0) densh[rrow] = denp;
        __syncthreads();

        #pragma unroll
        for (int mt = 0; mt < 4; mt++)
            #pragma unroll
            for (int half = 0; half < 2; half++){
                const int r = wm + mt*16 + lr + half*8;
                const float dinv = 1.f / (densh[r] + DEPS);
                #pragma unroll
                for (int nt = 0; nt < 2; nt++){
                    const int d0 = wno + nt*8 + 2*lc;
                    *(float2*)&g_o[((size_t)(b*SS + c*128 + r))*EE + h*DHH + d0] =
                        make_float2(acc[mt][nt][half*2+0]*dinv, acc[mt][nt][half*2+1]*dinv);
                }
            }
    }
}

// ---------------- head projection ----------------
__global__ __launch_bounds__(64) void head_kernel(const float* __restrict__ hw, float* __restrict__ out)
{
    __shared__ float xs[EE];
    const int r = blockIdx.x, t = threadIdx.x;
    ((float4*)xs)[t]      = ((const float4*)(g_x + (size_t)r*EE))[t];
    ((float4*)xs)[t + 64] = ((const float4*)(g_x + (size_t)r*EE))[t + 64];
    __syncthreads();
    if (t < NVOC){
        float acc = 0.f;
        #pragma unroll 8
        for (int k = 0; k < EE; k++) acc += xs[k] * hw[k*NVOC + t];
        out[(size_t)r*NVOC + t] = acc;
    }
}

// ---------------- host launch ----------------
extern "C" void kernel_launch(void* const* d_in, const int* in_sizes, int n_in,
                              void* d_out, int out_size)
{
    (void)in_sizes; (void)n_in; (void)out_size;
    const int*   value = (const int*)  d_in[0];
    const int*   depth = (const int*)  d_in[1];
    const int*   pos   = (const int*)  d_in[2];
    const float* proj  = (const float*)d_in[3];
    const float* sos   = (const float*)d_in[4];
    const float* tok   = (const float*)d_in[5];
    const float* dep   = (const float*)d_in[6];
    const float* spa   = (const float*)d_in[7];
    const float* ln1w  = (const float*)d_in[8];
    const float* ln1b  = (const float*)d_in[9];
    const float* Wq    = (const float*)d_in[10];
    const float* bq    = (const float*)d_in[11];
    const float* Wk    = (const float*)d_in[12];
    const float* bk    = (const float*)d_in[13];
    const float* Wv    = (const float*)d_in[14];
    const float* bv    = (const float*)d_in[15];
    const float* Wo    = (const float*)d_in[16];
    const float* bo    = (const float*)d_in[17];
    const float* ln2w  = (const float*)d_in[18];
    const float* ln2b  = (const float*)d_in[19];
    const float* W1    = (const float*)d_in[20];
    const float* b1    = (const float*)d_in[21];
    const float* W2    = (const float*)d_in[22];
    const float* b2    = (const float*)d_in[23];
    const float* hw    = (const float*)d_in[24];

    float *px, *ph, *pq, *pk, *pv, *po, *pff;
    cudaGetSymbolAddress((void**)&px,  g_x);
    cudaGetSymbolAddress((void**)&ph,  g_h);
    cudaGetSymbolAddress((void**)&pq,  g_q);
    cudaGetSymbolAddress((void**)&pk,  g_k);
    cudaGetSymbolAddress((void**)&pv,  g_v);
    cudaGetSymbolAddress((void**)&po,  g_o);
    cudaGetSymbolAddress((void**)&pff, g_ff);

    cudaFuncSetAttribute(po_kernel, cudaFuncAttributeMaxDynamicSharedMemorySize, PO_SMEM_BYTES);

    embed_kernel<<<(BSR*EE + 255)/256, 256>>>(value, depth, pos, sos, tok, dep, spa);
    prep_proj_kernel<<<(LL*DHH*MMF + 255)/256, 256>>>(proj);

    dim3 g512(4, 32);
    dim3 g2048(16, 32);
    dim3 gqkv(4, 32, 3);
    dim3 gfeat(NCH, BHH, 2);
    dim3 gchunk(NCH, BHH);
    dim3 gprefix(8, BHH);

    for (int l = 0; l < LL; l++){
        ln_kernel<<<BSR, 128>>>(px, ph, ln1w + l*EE, ln1b + l*EE);
        qkv_kernel<<<gqkv, 256>>>(ph,
            Wq + (size_t)l*EE*EE, Wk + (size_t)l*EE*EE, Wv + (size_t)l*EE*EE,
            bq + l*EE, bk + l*EE, bv + l*EE,
            pq, pk, pv);

        feat_kernel<<<gfeat, 256>>>(l);
        kvz_kernel<<<gchunk, 256>>>(l);
        chunk_prefix_kernel<<<gprefix, 1024>>>();
        po_kernel<<<gchunk, 256, PO_SMEM_BYTES>>>();

        tgemm_kernel<<<g512, 256>>>(po, Wo + (size_t)l*EE*EE, bo + l*EE, px, px, EE, EE, 0);
        ln_kernel<<<BSR, 128>>>(px, ph, ln2w + l*EE, ln2b + l*EE);
        tgemm_kernel<<<g2048, 256>>>(ph, W1 + (size_t)l*EE*FFD, b1 + l*FFD, nullptr, pff, FFD, EE, 1);
        tgemm_kernel<<<g512, 256>>>(pff, W2 + (size_t)l*FFD*EE, b2 + l*EE, px, px, EE, FFD, 0);
    }

    head_kernel<<<BSR, 64>>>(hw, (float*)d_out);
}

// round 10
// speedup vs baseline: 1.1077x; 1.0576x over previous
#include <cuda_runtime.h>
#include <cuda_bf16.h>
#include <math.h>

// ---------------- problem constants ----------------
#define BB   2
#define SS   2048
#define EE   512
#define HH   8
#define LL   4
#define DHH  64
#define MMF  128
#define AAX  3
#define NVOC 17
#define BHH  (BB*HH)      // 16
#define BSR  (BB*SS)      // 4096
#define NCH  (SS/128)     // 16
#define FFD  (4*EE)       // 2048

#define DNQ   0.3535533905932738f
#define RATIO 0.08838834764831845f
#define KEPS  1e-4f
#define DEPS  1e-6f

// ---------------- scratch ----------------
__device__ float g_x [BSR*EE];
__device__ float g_h [BSR*EE];
__device__ float g_q [BSR*EE];
__device__ float g_k [BSR*EE];
__device__ float g_v [BSR*EE];
__device__ float g_o [BSR*EE];
__device__ float g_ff[BSR*FFD];
__device__ float g_qp[BHH*SS*MMF];
__device__ float g_kp[BHH*SS*MMF];
__device__ unsigned g_kmaxv[LL];
__device__ float g_Sc[BHH*NCH*MMF*DHH];
__device__ float g_Sp[BHH*NCH*MMF*DHH];
__device__ float g_zc[BHH*NCH*MMF];
__device__ float g_zp[BHH*NCH*MMF];
__device__ unsigned g_projh[LL*DHH*MMF];   // transposed [l][k][m], tf32 hi
__device__ unsigned g_projl[LL*DHH*MMF];   // transposed [l][k][m], tf32 lo

// ---------------- helpers ----------------
__device__ __forceinline__ unsigned f_enc(float f){
    unsigned u = __float_as_uint(f);
    return (u & 0x80000000u) ? ~u : (u | 0x80000000u);
}
__device__ __forceinline__ float f_dec(unsigned u){
    return (u & 0x80000000u) ? __uint_as_float(u & 0x7fffffffu) : __uint_as_float(~u);
}
__device__ __forceinline__ unsigned f2tf(float x){
    unsigned r; asm("cvt.rna.tf32.f32 %0, %1;" : "=r"(r) : "f"(x)); return r;
}
// A-row interleave: within each 16-row group store m0,m8,m1,m9,... so fragment
// row pairs (r, r+8) are adjacent -> LDS.64
__device__ __forceinline__ int permA(int m){
    return (m & ~15) | ((m & 7) << 1) | ((m >> 3) & 1);
}

#define MMA_TF32(c, a, b) asm volatile( \
  "mma.sync.aligned.m16n8k8.row.col.f32.tf32.tf32.f32 " \
  "{%0,%1,%2,%3}, {%4,%5,%6,%7}, {%8,%9}, {%0,%1,%2,%3};" \
  : "+f"(c[0]),"+f"(c[1]),"+f"(c[2]),"+f"(c[3]) \
  : "r"(a[0]),"r"(a[1]),"r"(a[2]),"r"(a[3]), "r"(b[0]),"r"(b[1]))

__device__ __forceinline__ void tfsplit(float x, unsigned& hi, unsigned& lo){
    hi = f2tf(x);
    lo = f2tf(x - __uint_as_float(hi));
}

// ---------------- embedding (+ per-layer kmax reset) ----------------
__global__ void embed_kernel(const int* __restrict__ value, const int* __restrict__ depth,
                             const int* __restrict__ pos,   const float* __restrict__ sos,
                             const float* __restrict__ tok, const float* __restrict__ dep,
                             const float* __restrict__ spa)
{
    if (blockIdx.x == 0 && threadIdx.x < LL) g_kmaxv[threadIdx.x] = 0u;
    int i = blockIdx.x * 256 + threadIdx.x;
    if (i >= BSR*EE) return;
    int e = i & (EE-1);
    int r = i >> 9;
    int b = r / SS, s = r - b*SS;
    float val;
    if (s == 0) val = sos[e];
    else {
        int p = b*SS + s - 1;
        val = tok[value[p]*EE + e] + dep[depth[p]*EE + e];
        #pragma unroll
        for (int a = 0; a < AAX; a++)
            val += spa[(size_t)a*65*EE + pos[p*AAX + a]*EE + e];
    }
    g_x[i] = val;
}

// ---------------- proj precompute: transposed hi/lo splits ----------------
__global__ void prep_proj_kernel(const float* __restrict__ proj)
{
    int i = blockIdx.x * 256 + threadIdx.x;      // i over LL*DHH*MMF
    if (i >= LL*DHH*MMF) return;
    int l = i / (DHH*MMF);
    int rem = i - l*(DHH*MMF);
    int k = rem >> 7;            // 0..63
    int m = rem & 127;           // 0..127
    float v = proj[(size_t)l*MMF*DHH + m*DHH + k];
    unsigned hi, lo; tfsplit(v, hi, lo);
    g_projh[i] = hi;
    g_projl[i] = lo;
}

// ---------------- layernorm ----------------
__global__ __launch_bounds__(128) void ln_kernel(const float* __restrict__ in, float* __restrict__ out,
                                                 const float* __restrict__ w, const float* __restrict__ bia)
{
    int r = blockIdx.x, t = threadIdx.x;
    const float4 v = ((const float4*)(in + (size_t)r*EE))[t];
    float s  = v.x + v.y + v.z + v.w;
    float sq = v.x*v.x + v.y*v.y + v.z*v.z + v.w*v.w;
    #pragma unroll
    for (int o = 16; o; o >>= 1){ s += __shfl_xor_sync(~0u, s, o); sq += __shfl_xor_sync(~0u, sq, o); }
    __shared__ float sh[8];
    if ((t & 31) == 0){ sh[t>>5] = s; sh[4 + (t>>5)] = sq; }
    __syncthreads();
    s  = sh[0]+sh[1]+sh[2]+sh[3];
    sq = sh[4]+sh[5]+sh[6]+sh[7];
    float mu  = s * (1.f/EE);
    float var = sq * (1.f/EE) - mu*mu;
    float rs  = rsqrtf(var + 1e-5f);
    float4 wv = ((const float4*)w)[t], bv = ((const float4*)bia)[t];
    float4 o4;
    o4.x = (v.x-mu)*rs*wv.x + bv.x;
    o4.y = (v.y-mu)*rs*wv.y + bv.y;
    o4.z = (v.z-mu)*rs*wv.z + bv.z;
    o4.w = (v.w-mu)*rs*wv.w + bv.w;
    ((float4*)(out + (size_t)r*EE))[t] = o4;
}

// ---------------- tf32 GEMM (weights) — interleaved A rows, LDS.64 A frags ----------------
#define BKK 16
#define LDA 136
#define LDB 136

__device__ __forceinline__ void gemm_body(
    const float* __restrict__ Am, const float* __restrict__ Bm,
    const float* __restrict__ bias, const float* __restrict__ resid,
    float* __restrict__ C, int N, int K, int act,
    unsigned* As, unsigned* Bs)
{
    const int tid = threadIdx.x;
    const int bm = blockIdx.y * 128, bn = blockIdx.x * 128;
    const int w = tid >> 5, lane = tid & 31;
    const int wm = (w & 1) * 64, wn = (w >> 1) * 32;
    const int lr = lane >> 2, lc = lane & 3;

    float acc[4][4][4];
    #pragma unroll
    for (int i = 0; i < 4; i++)
        #pragma unroll
        for (int j = 0; j < 4; j++)
            #pragma unroll
            for (int t = 0; t < 4; t++) acc[i][j][t] = 0.f;

    const int f0 = tid, f1 = tid + 256;
    const int ar0 = f0 >> 2, ak0 = (f0 & 3) << 2;
    const int ar1 = f1 >> 2, ak1 = (f1 & 3) << 2;
    const int br0 = f0 >> 5, bc0 = (f0 & 31) << 2;
    const int br1 = f1 >> 5, bc1 = (f1 & 31) << 2;
    const int pa0 = permA(ar0), pa1 = permA(ar1);

    float4 a4[2], b4[2];
    const int nk = K / BKK;

    a4[0] = *(const float4*)&Am[(size_t)(bm + ar0)*K + ak0];
    a4[1] = *(const float4*)&Am[(size_t)(bm + ar1)*K + ak1];
    b4[0] = *(const float4*)&Bm[(size_t)br0*N + bn + bc0];
    b4[1] = *(const float4*)&Bm[(size_t)br1*N + bn + bc1];
    {
        unsigned* Ab = As; unsigned* Bb = Bs;
        Ab[(ak0+0)*LDA + pa0] = f2tf(a4[0].x); Ab[(ak0+1)*LDA + pa0] = f2tf(a4[0].y);
        Ab[(ak0+2)*LDA + pa0] = f2tf(a4[0].z); Ab[(ak0+3)*LDA + pa0] = f2tf(a4[0].w);
        Ab[(ak1+0)*LDA + pa1] = f2tf(a4[1].x); Ab[(ak1+1)*LDA + pa1] = f2tf(a4[1].y);
        Ab[(ak1+2)*LDA + pa1] = f2tf(a4[1].z); Ab[(ak1+3)*LDA + pa1] = f2tf(a4[1].w);
        uint4 bv0 = make_uint4(f2tf(b4[0].x), f2tf(b4[0].y), f2tf(b4[0].z), f2tf(b4[0].w));
        uint4 bv1 = make_uint4(f2tf(b4[1].x), f2tf(b4[1].y), f2tf(b4[1].z), f2tf(b4[1].w));
        *(uint4*)&Bb[br0*LDB + bc0] = bv0;
        *(uint4*)&Bb[br1*LDB + bc1] = bv1;
    }
    __syncthreads();

    for (int it = 0; it < nk; it++){
        const int cur = it & 1;
        if (it + 1 < nk){
            const int k0 = (it + 1) * BKK;
            a4[0] = *(const float4*)&Am[(size_t)(bm + ar0)*K + k0 + ak0];
            a4[1] = *(const float4*)&Am[(size_t)(bm + ar1)*K + k0 + ak1];
            b4[0] = *(const float4*)&Bm[(size_t)(k0 + br0)*N + bn + bc0];
            b4[1] = *(const float4*)&Bm[(size_t)(k0 + br1)*N + bn + bc1];
        }
        {
            const unsigned* Ab = As + cur * (BKK * LDA);
            const unsigned* Bb = Bs + cur * (BKK * LDB);
            #pragma unroll
            for (int ks = 0; ks < BKK; ks += 8){
                unsigned af[4][4], bf[4][2];
                #pragma unroll
                for (int mt = 0; mt < 4; mt++){
                    const int base = (ks + lc)*LDA + wm + mt*16 + lr*2;
                    uint2 x0 = *(const uint2*)&Ab[base];
                    uint2 x1 = *(const uint2*)&Ab[base + 4*LDA];
                    af[mt][0] = x0.x; af[mt][1] = x0.y;
                    af[mt][2] = x1.x; af[mt][3] = x1.y;
                }
                #pragma unroll
                for (int nt = 0; nt < 4; nt++){
                    const int base = (ks + lc)*LDB + wn + nt*8 + lr;
                    bf[nt][0] = Bb[base];
                    bf[nt][1] = Bb[base + 4*LDB];
                }
                #pragma unroll
                for (int mt = 0; mt < 4; mt++)
                    #pragma unroll
                    for (int nt = 0; nt < 4; nt++)
                        MMA_TF32(acc[mt][nt], af[mt], bf[nt]);
            }
        }
        if (it + 1 < nk){
            unsigned* Ab = As + (cur ^ 1) * (BKK * LDA);
            unsigned* Bb = Bs + (cur ^ 1) * (BKK * LDB);
            Ab[(ak0+0)*LDA + pa0] = f2tf(a4[0].x); Ab[(ak0+1)*LDA + pa0] = f2tf(a4[0].y);
            Ab[(ak0+2)*LDA + pa0] = f2tf(a4[0].z); Ab[(ak0+3)*LDA + pa0] = f2tf(a4[0].w);
            Ab[(ak1+0)*LDA + pa1] = f2tf(a4[1].x); Ab[(ak1+1)*LDA + pa1] = f2tf(a4[1].y);
            Ab[(ak1+2)*LDA + pa1] = f2tf(a4[1].z); Ab[(ak1+3)*LDA + pa1] = f2tf(a4[1].w);
            uint4 bv0 = make_uint4(f2tf(b4[0].x), f2tf(b4[0].y), f2tf(b4[0].z), f2tf(b4[0].w));
            uint4 bv1 = make_uint4(f2tf(b4[1].x), f2tf(b4[1].y), f2tf(b4[1].z), f2tf(b4[1].w));
            *(uint4*)&Bb[br0*LDB + bc0] = bv0;
            *(uint4*)&Bb[br1*LDB + bc1] = bv1;
        }
        __syncthreads();
    }

    #pragma unroll
    for (int mt = 0; mt < 4; mt++){
        const int r0 = bm + wm + mt*16 + lr;
        #pragma unroll
        for (int nt = 0; nt < 4; nt++){
            const int c0 = bn + wn + nt*8 + 2*lc;
            const float bx = bias[c0], by = bias[c0+1];
            #pragma unroll
            for (int half = 0; half < 2; half++){
                const int r = r0 + half*8;
                float v0 = acc[mt][nt][half*2+0] + bx;
                float v1 = acc[mt][nt][half*2+1] + by;
                if (act){
                    v0 = 0.5f*v0*(1.f + erff(v0*0.70710678118654752f));
                    v1 = 0.5f*v1*(1.f + erff(v1*0.70710678118654752f));
                }
                if (resid){
                    v0 += resid[(size_t)r*N + c0];
                    v1 += resid[(size_t)r*N + c0+1];
                }
                *(float2*)&C[(size_t)r*N + c0] = make_float2(v0, v1);
            }
        }
    }
}

__global__ __launch_bounds__(256, 2) void tgemm_kernel(
    const float* __restrict__ A, const float* __restrict__ Bm,
    const float* __restrict__ bias, const float* __restrict__ resid,
    float* __restrict__ C, int N, int K, int act)
{
    __shared__ __align__(16) unsigned As[2*BKK*LDA];
    __shared__ __align__(16) unsigned Bs[2*BKK*LDB];
    gemm_body(A, Bm, bias, resid, C, N, K, act, As, Bs);
}

__global__ __launch_bounds__(256, 2) void qkv_kernel(
    const float* __restrict__ A,
    const float* __restrict__ Wq, const float* __restrict__ Wk, const float* __restrict__ Wv,
    const float* __restrict__ bq, const float* __restrict__ bk, const float* __restrict__ bv,
    float* __restrict__ oq, float* __restrict__ ok, float* __restrict__ ov)
{
    __shared__ __align__(16) unsigned As[2*BKK*LDA];
    __shared__ __align__(16) unsigned Bs[2*BKK*LDB];
    const int z = blockIdx.z;
    const float* Bm  = (z == 0) ? Wq : (z == 1) ? Wk : Wv;
    const float* bi  = (z == 0) ? bq : (z == 1) ? bk : bv;
    float*       Cm  = (z == 0) ? oq : (z == 1) ? ok : ov;
    gemm_body(A, Bm, bi, nullptr, Cm, EE, EE, 0, As, Bs);
}

// helper: load interleaved hi/lo A fragments (LDS.64 pairs)
#define LOAD_AFRAG(afh, afl, Ah, Al, base) do { \
    uint2 _h0 = *(const uint2*)&(Ah)[(base)]; \
    uint2 _h1 = *(const uint2*)&(Ah)[(base) + 4*LDA]; \
    uint2 _l0 = *(const uint2*)&(Al)[(base)]; \
    uint2 _l1 = *(const uint2*)&(Al)[(base) + 4*LDA]; \
    (afh)[0] = _h0.x; (afh)[1] = _h0.y; (afh)[2] = _h1.x; (afh)[3] = _h1.y; \
    (afl)[0] = _l0.x; (afl)[1] = _l0.y; (afl)[2] = _l1.x; (afl)[3] = _l1.y; \
} while(0)

// ================= FAVOR features via 3xTF32 MMA (precomputed proj splits) ===========
__global__ __launch_bounds__(256) void feat_kernel(int l)
{
    __shared__ __align__(16) unsigned Ah[16*LDA], Al[16*LDA], Bh[16*LDB], Bl[16*LDB];
    __shared__ float diag[128];
    __shared__ unsigned rmax[128];
    __shared__ unsigned bmax;
    const int tid = threadIdx.x;
    const int c = blockIdx.x, bh = blockIdx.y;
    const int isq = (blockIdx.z == 0);
    const int b = bh / HH, h = bh % HH;
    const float* src = isq ? g_q : g_k;
    const unsigned* prjh = g_projh + (size_t)l*DHH*MMF;
    const unsigned* prjl = g_projl + (size_t)l*DHH*MMF;
    const int w = tid >> 5, lane = tid & 31;
    const int wm = (w & 1) * 64, wn = (w >> 1) * 32;
    const int lr = lane >> 2, lc = lane & 3;

    if (tid < 128) rmax[tid] = 0u;
    if (tid == 0) bmax = 0u;

    float acc[4][4][4];
    #pragma unroll
    for (int i = 0; i < 4; i++)
        #pragma unroll
        for (int j = 0; j < 4; j++)
            #pragma unroll
            for (int t = 0; t < 4; t++) acc[i][j][t] = 0.f;

    const int rrow = tid >> 1, kg = (tid & 1) * 8;
    const int prow = permA(rrow);
    const int bk = tid >> 4, bm0 = (tid & 15) * 8;     // B staging (transposed layout)
    float sq = 0.f;

    for (int kit = 0; kit < 4; kit++){
        const int k0 = kit * 16;
        // A: x rows (scaled) — staged k-major with tfsplit, interleaved m
        #pragma unroll
        for (int q4 = 0; q4 < 2; q4++){
            float4 a = *(const float4*)&src[((size_t)(b*SS + c*128 + rrow))*EE + h*DHH + k0 + kg + q4*4];
            float vals[4] = {a.x*DNQ, a.y*DNQ, a.z*DNQ, a.w*DNQ};
            #pragma unroll
            for (int i = 0; i < 4; i++){
                sq += vals[i]*vals[i];
                unsigned hi, lo; tfsplit(vals[i], hi, lo);
                Ah[(kg + q4*4 + i)*LDA + prow] = hi;
                Al[(kg + q4*4 + i)*LDA + prow] = lo;
            }
        }
        // B: precomputed transposed hi/lo proj — vector copies
        {
            const size_t pb = (size_t)(k0 + bk)*MMF + bm0;
            uint4 h0 = *(const uint4*)&prjh[pb];
            uint4 h1 = *(const uint4*)&prjh[pb + 4];
            uint4 l0 = *(const uint4*)&prjl[pb];
            uint4 l1 = *(const uint4*)&prjl[pb + 4];
            *(uint4*)&Bh[bk*LDB + bm0]     = h0;
            *(uint4*)&Bh[bk*LDB + bm0 + 4] = h1;
            *(uint4*)&Bl[bk*LDB + bm0]     = l0;
            *(uint4*)&Bl[bk*LDB + bm0 + 4] = l1;
        }
        __syncthreads();
        #pragma unroll
        for (int ks = 0; ks < 16; ks += 8){
            unsigned afh[4][4], afl[4][4], bfh[4][2], bfl[4][2];
            #pragma unroll
            for (int mt = 0; mt < 4; mt++){
                const int base = (ks + lc)*LDA + wm + mt*16 + lr*2;
                LOAD_AFRAG(afh[mt], afl[mt], Ah, Al, base);
            }
            #pragma unroll
            for (int nt = 0; nt < 4; nt++){
                const int base = (ks + lc)*LDB + wn + nt*8 + lr;
                bfh[nt][0] = Bh[base];         bfl[nt][0] = Bl[base];
                bfh[nt][1] = Bh[base + 4*LDB]; bfl[nt][1] = Bl[base + 4*LDB];
            }
            #pragma unroll
            for (int mt = 0; mt < 4; mt++)
                #pragma unroll
                for (int nt = 0; nt < 4; nt++){
                    MMA_TF32(acc[mt][nt], afh[mt], bfh[nt]);
                    MMA_TF32(acc[mt][nt], afh[mt], bfl[nt]);
                    MMA_TF32(acc[mt][nt], afl[mt], bfh[nt]);
                }
        }
        __syncthreads();
    }
    {
        float other = __shfl_xor_sync(~0u, sq, 1);
        if ((tid & 1) == 0) diag[rrow] = 0.5f * (sq + other);
    }
    if (isq){
        #pragma unroll
        for (int mt = 0; mt < 4; mt++)
            #pragma unroll
            for (int half = 0; half < 2; half++){
                const int r = wm + mt*16 + lr + half*8;
                float m = -3.4e38f;
                #pragma unroll
                for (int nt = 0; nt < 4; nt++){
                    m = fmaxf(m, acc[mt][nt][half*2+0]);
                    m = fmaxf(m, acc[mt][nt][half*2+1]);
                }
                atomicMax(&rmax[r], f_enc(m));
            }
    } else {
        float m = -3.4e38f;
        #pragma unroll
        for (int mt = 0; mt < 4; mt++)
            #pragma unroll
            for (int nt = 0; nt < 4; nt++)
                #pragma unroll
                for (int t = 0; t < 4; t++) m = fmaxf(m, acc[mt][nt][t]);
        #pragma unroll
        for (int o = 16; o; o >>= 1) m = fmaxf(m, __shfl_xor_sync(~0u, m, o));
        if (lane == 0) atomicMax(&bmax, f_enc(m));
    }
    __syncthreads();

    const size_t qbase = (size_t)bh*SS + c*128;
    if (isq){
        #pragma unroll
        for (int mt = 0; mt < 4; mt++)
            #pragma unroll
            for (int half = 0; half < 2; half++){
                const int r = wm + mt*16 + lr + half*8;
                const float dg = diag[r], mx = f_dec(rmax[r]);
                #pragma unroll
                for (int nt = 0; nt < 4; nt++){
                    const int c0 = wn + nt*8 + 2*lc;
                    float v0 = RATIO*(expf(acc[mt][nt][half*2+0] - dg - mx) + KEPS);
                    float v1 = RATIO*(expf(acc[mt][nt][half*2+1] - dg - mx) + KEPS);
                    *(float2*)&g_qp[(qbase + r)*MMF + c0] = make_float2(v0, v1);
                }
            }
    } else {
        if (tid == 0) atomicMax(&g_kmaxv[l], bmax);
        #pragma unroll
        for (int mt = 0; mt < 4; mt++)
            #pragma unroll
            for (int half = 0; half < 2; half++){
                const int r = wm + mt*16 + lr + half*8;
                const float dg = diag[r];
                #pragma unroll
                for (int nt = 0; nt < 4; nt++){
                    const int c0 = wn + nt*8 + 2*lc;
                    float v0 = acc[mt][nt][half*2+0] - dg;
                    float v1 = acc[mt][nt][half*2+1] - dg;
                    *(float2*)&g_kp[(qbase + r)*MMF + c0] = make_float2(v0, v1);
                }
            }
    }
}

// ========== fused: kp exp-transform + writeback + zc + Sc (3xTF32 MMA) ==========
#define KVLDB 72
__global__ __launch_bounds__(256, 2) void kvz_kernel(int l)
{
    __shared__ __align__(16) unsigned Ah[16*LDA], Al[16*LDA], Bh[16*KVLDB], Bl[16*KVLDB];
    __shared__ float zcs[128];
    const int c = blockIdx.x, bh = blockIdx.y;
    const int b = bh / HH, h = bh % HH;
    const int tid = threadIdx.x;
    const int w = tid >> 5, lane = tid & 31;
    const int wm = (w & 1) * 64, wn = (w >> 1) * 16;
    const int lr = lane >> 2, lc = lane & 3;
    const size_t qbase = (size_t)bh*SS + c*128;
    const float gm = f_dec(g_kmaxv[l]);

    if (tid < 128) zcs[tid] = 0.f;

    float acc[4][2][4];
    #pragma unroll
    for (int i = 0; i < 4; i++)
        #pragma unroll
        for (int j = 0; j < 2; j++)
            #pragma unroll
            for (int t = 0; t < 4; t++) acc[i][j][t] = 0.f;

    const int at = tid >> 4, am0 = (tid & 15) * 8;
    const int bt = tid >> 4, bd0 = (tid & 15) * 4;
    float zcp[8];
    #pragma unroll
    for (int i = 0; i < 8; i++) zcp[i] = 0.f;

    for (int kit = 0; kit < 8; kit++){
        const int t0 = kit * 16;
        #pragma unroll
        for (int q4 = 0; q4 < 2; q4++){
            size_t off = (qbase + t0 + at)*MMF + am0 + q4*4;
            float4 a = *(const float4*)&g_kp[off];
            float vals[4];
            vals[0] = RATIO*(expf(a.x - gm) + KEPS);
            vals[1] = RATIO*(expf(a.y - gm) + KEPS);
            vals[2] = RATIO*(expf(a.z - gm) + KEPS);
            vals[3] = RATIO*(expf(a.w - gm) + KEPS);
            *(float4*)&g_kp[off] = make_float4(vals[0], vals[1], vals[2], vals[3]);
            #pragma unroll
            for (int i = 0; i < 4; i++){
                zcp[q4*4 + i] += vals[i];
                unsigned hi, lo; tfsplit(vals[i], hi, lo);
                const int pm = permA(am0 + q4*4 + i);
                Ah[at*LDA + pm] = hi;
                Al[at*LDA + pm] = lo;
            }
        }
        {
            float4 vv = *(const float4*)&g_v[((size_t)(b*SS + c*128 + t0 + bt))*EE + h*DHH + bd0];
            float vals[4] = {vv.x, vv.y, vv.z, vv.w};
            #pragma unroll
            for (int i = 0; i < 4; i++){
                unsigned hi, lo; tfsplit(vals[i], hi, lo);
                Bh[bt*KVLDB + bd0 + i] = hi;
                Bl[bt*KVLDB + bd0 + i] = lo;
            }
        }
        __syncthreads();
        #pragma unroll
        for (int ks = 0; ks < 16; ks += 8){
            unsigned afh[4][4], afl[4][4], bfh[2][2], bfl[2][2];
            #pragma unroll
            for (int mt = 0; mt < 4; mt++){
                const int base = (ks + lc)*LDA + wm + mt*16 + lr*2;
                LOAD_AFRAG(afh[mt], afl[mt], Ah, Al, base);
            }
            #pragma unroll
            for (int nt = 0; nt < 2; nt++){
                const int base = (ks + lc)*KVLDB + wn + nt*8 + lr;
                bfh[nt][0] = Bh[base];           bfl[nt][0] = Bl[base];
                bfh[nt][1] = Bh[base + 4*KVLDB]; bfl[nt][1] = Bl[base + 4*KVLDB];
            }
            #pragma unroll
            for (int mt = 0; mt < 4; mt++)
                #pragma unroll
                for (int nt = 0; nt < 2; nt++){
                    MMA_TF32(acc[mt][nt], afh[mt], bfh[nt]);
                    MMA_TF32(acc[mt][nt], afh[mt], bfl[nt]);
                    MMA_TF32(acc[mt][nt], afl[mt], bfh[nt]);
                }
        }
        __syncthreads();
    }
    #pragma unroll
    for (int i = 0; i < 8; i++) atomicAdd(&zcs[am0 + i], zcp[i]);
    __syncthreads();
    if (tid < 128) g_zc[(bh*NCH + c)*MMF + tid] = zcs[tid];

    const size_t base = ((size_t)(bh*NCH + c))*MMF;
    #pragma unroll
    for (int mt = 0; mt < 4; mt++)
        #pragma unroll
        for (int half = 0; half < 2; half++){
            const int m = wm + mt*16 + lr + half*8;
            #pragma unroll
            for (int nt = 0; nt < 2; nt++){
                const int d0 = wn + nt*8 + 2*lc;
                *(float2*)&g_Sc[(base + m)*DHH + d0] =
                    make_float2(acc[mt][nt][half*2+0], acc[mt][nt][half*2+1]);
            }
        }
}

// ---------------- parallel exclusive prefix over chunks ----------------
__global__ __launch_bounds__(1024) void chunk_prefix_kernel()
{
    const int bh = blockIdx.y;
    const int idx = blockIdx.x * 1024 + threadIdx.x;
    float run = 0.f;
    #pragma unroll
    for (int c = 0; c < NCH; c++){
        size_t off = ((size_t)(bh*NCH + c))*MMF*DHH + idx;
        float v = g_Sc[off];
        g_Sp[off] = run;
        run += v;
    }
    if (blockIdx.x == 0 && threadIdx.x < MMF){
        const int m = threadIdx.x;
        float rz = 0.f;
        #pragma unroll
        for (int c = 0; c < NCH; c++){
            int zb = (bh*NCH + c)*MMF + m;
            g_zp[zb] = rz;
            rz += g_zc[zb];
        }
    }
}

// ======= FUSED: P = mask(qp@kp^T) in smem, then out = ([P|qp]@[v;Sp])/den =======
#define LDP 132
#define PO_PS_WORDS (128*LDP)          // 16896
#define PO_AB_WORDS (16*LDA)           // 2176
#define PO_SMEM_BYTES ((PO_PS_WORDS + 4*PO_AB_WORDS + 128) * 4)   // 102912 B

__global__ __launch_bounds__(256) void po_kernel()
{
    extern __shared__ __align__(16) float po_smem[];
    float*    Ps    = po_smem;
    unsigned* Ah    = (unsigned*)(po_smem + PO_PS_WORDS);
    unsigned* Al    = Ah + PO_AB_WORDS;
    unsigned* Bh    = Al + PO_AB_WORDS;
    unsigned* Bl    = Bh + PO_AB_WORDS;
    float*    densh = (float*)(Bl + PO_AB_WORDS);

    const int c = blockIdx.x, bh = blockIdx.y;
    const int b = bh / HH, h = bh % HH;
    const int tid = threadIdx.x;
    const int w = tid >> 5, lane = tid & 31;
    const int wm = (w & 1) * 64;
    const int wnp = (w >> 1) * 32;
    const int wno = (w >> 1) * 16;
    const int lr = lane >> 2, lc = lane & 3;
    const size_t qbase = (size_t)bh*SS + c*128;
    const size_t sbase = ((size_t)(bh*NCH + c))*MMF;
    const int rrow = tid >> 1, kg = (tid & 1) * 8;
    const int prow = permA(rrow);

    // ---------------- phase 1: P = mask(qp @ kp^T) ----------------
    {
        float acc[4][4][4];
        #pragma unroll
        for (int i = 0; i < 4; i++)
            #pragma unroll
            for (int j = 0; j < 4; j++)
                #pragma unroll
                for (int t = 0; t < 4; t++) acc[i][j][t] = 0.f;

        for (int kit = 0; kit < 8; kit++){
            const int m0 = kit * 16;
            #pragma unroll
            for (int q4 = 0; q4 < 2; q4++){
                float4 a = *(const float4*)&g_qp[(qbase + rrow)*MMF + m0 + kg + q4*4];
                float va[4] = {a.x, a.y, a.z, a.w};
                float4 bk = *(const float4*)&g_kp[(qbase + rrow)*MMF + m0 + kg + q4*4];
                float vb[4] = {bk.x, bk.y, bk.z, bk.w};
                #pragma unroll
                for (int i = 0; i < 4; i++){
                    unsigned hi, lo;
                    tfsplit(va[i], hi, lo);
                    Ah[(kg + q4*4 + i)*LDA + prow] = hi;
                    Al[(kg + q4*4 + i)*LDA + prow] = lo;
                    tfsplit(vb[i], hi, lo);
                    Bh[(kg + q4*4 + i)*LDB + rrow] = hi;
                    Bl[(kg + q4*4 + i)*LDB + rrow] = lo;
                }
            }
            __syncthreads();
            #pragma unroll
            for (int ks = 0; ks < 16; ks += 8){
                unsigned afh[4][4], afl[4][4], bfh[4][2], bfl[4][2];
                #pragma unroll
                for (int mt = 0; mt < 4; mt++){
                    const int base = (ks + lc)*LDA + wm + mt*16 + lr*2;
                    LOAD_AFRAG(afh[mt], afl[mt], Ah, Al, base);
                }
                #pragma unroll
                for (int nt = 0; nt < 4; nt++){
                    const int base = (ks + lc)*LDB + wnp + nt*8 + lr;
                    bfh[nt][0] = Bh[base];         bfl[nt][0] = Bl[base];
                    bfh[nt][1] = Bh[base + 4*LDB]; bfl[nt][1] = Bl[base + 4*LDB];
                }
                #pragma unroll
                for (int mt = 0; mt < 4; mt++)
                    #pragma unroll
                    for (int nt = 0; nt < 4; nt++){
                        MMA_TF32(acc[mt][nt], afh[mt], bfh[nt]);
                        MMA_TF32(acc[mt][nt], afh[mt], bfl[nt]);
                        MMA_TF32(acc[mt][nt], afl[mt], bfh[nt]);
                    }
            }
            __syncthreads();
        }
        #pragma unroll
        for (int mt = 0; mt < 4; mt++)
            #pragma unroll
            for (int half = 0; half < 2; half++){
                const int r = wm + mt*16 + lr + half*8;
                #pragma unroll
                for (int nt = 0; nt < 4; nt++){
                    const int c0 = wnp + nt*8 + 2*lc;
                    float v0 = (c0   <= r) ? acc[mt][nt][half*2+0] : 0.f;
                    float v1 = (c0+1 <= r) ? acc[mt][nt][half*2+1] : 0.f;
                    *(float2*)&Ps[r*LDP + c0] = make_float2(v0, v1);
                }
            }
    }
    __syncthreads();

    // ------- phase 2: out = ([P|qp] @ [v;Sp]) / den, den fused in staging -------
    {
        float acc[4][2][4];
        #pragma unroll
        for (int i = 0; i < 4; i++)
            #pragma unroll
            for (int j = 0; j < 2; j++)
                #pragma unroll
                for (int t = 0; t < 4; t++) acc[i][j][t] = 0.f;

        const int bt = tid >> 4, bd0 = (tid & 15) * 4;
        float denp = 0.f;

        for (int kit = 0; kit < 16; kit++){
            const int j0 = kit * 16;
            #pragma unroll
            for (int q4 = 0; q4 < 2; q4++){
                float4 a;
                if (j0 < 128) a = *(const float4*)&Ps[rrow*LDP + j0 + kg + q4*4];
                else          a = *(const float4*)&g_qp[(qbase + rrow)*MMF + (j0 - 128) + kg + q4*4];
                float vals[4] = {a.x, a.y, a.z, a.w};
                if (j0 < 128){
                    denp += vals[0] + vals[1] + vals[2] + vals[3];
                } else {
                    float4 zpv = *(const float4*)&g_zp[sbase + (j0 - 128) + kg + q4*4];
                    denp += vals[0]*zpv.x + vals[1]*zpv.y + vals[2]*zpv.z + vals[3]*zpv.w;
                }
                #pragma unroll
                for (int i = 0; i < 4; i++){
                    unsigned hi, lo; tfsplit(vals[i], hi, lo);
                    Ah[(kg + q4*4 + i)*LDA + prow] = hi;
                    Al[(kg + q4*4 + i)*LDA + prow] = lo;
                }
            }
            {
                float4 hv;
                if (j0 < 128) hv = *(const float4*)&g_v[((size_t)(b*SS + c*128 + j0 + bt))*EE + h*DHH + bd0];
                else          hv = *(const float4*)&g_Sp[(sbase + (j0 - 128) + bt)*DHH + bd0];
                float vals[4] = {hv.x, hv.y, hv.z, hv.w};
                #pragma unroll
                for (int i = 0; i < 4; i++){
                    unsigned hi, lo; tfsplit(vals[i], hi, lo);
                    Bh[bt*KVLDB + bd0 + i] = hi;
                    Bl[bt*KVLDB + bd0 + i] = lo;
                }
            }
            __syncthreads();
            #pragma unroll
            for (int ks = 0; ks < 16; ks += 8){
                unsigned afh[4][4], afl[4][4], bfh[2][2], bfl[2][2];
                #pragma unroll
                for (int mt = 0; mt < 4; mt++){
                    const int base = (ks + lc)*LDA + wm + mt*16 + lr*2;
                    LOAD_AFRAG(afh[mt], afl[mt], Ah, Al, base);
                }
                #pragma unroll
                for (int nt = 0; nt < 2; nt++){
                    const int base = (ks + lc)*KVLDB + wno + nt*8 + lr;
                    bfh[nt][0] = Bh[base];           bfl[nt][0] = Bl[base];
                    bfh[nt][1] = Bh[base + 4*KVLDB]; bfl[nt][1] = Bl[base + 4*KVLDB];
                }
                #pragma unroll
                for (int mt = 0; mt < 4; mt++)
                    #pragma unroll
                    for (int nt = 0; nt < 2; nt++){
                        MMA_TF32(acc[mt][nt], afh[mt], bfh[nt]);
                        MMA_TF32(acc[mt][nt], afh[mt], bfl[nt]);
                        MMA_TF32(acc[mt][nt], afl[mt], bfh[nt]);
                    }
            }
            __syncthreads();
        }
        denp += __shfl_xor_sync(~0u, denp, 1);
        if ((tid & 1) == 0) densh[rrow] = denp;
        __syncthreads();

        #pragma unroll
        for (int mt = 0; mt < 4; mt++)
            #pragma unroll
            for (int half = 0; half < 2; half++){
                const int r = wm + mt*16 + lr + half*8;
                const float dinv = 1.f / (densh[r] + DEPS);
                #pragma unroll
                for (int nt = 0; nt < 2; nt++){
                    const int d0 = wno + nt*8 + 2*lc;
                    *(float2*)&g_o[((size_t)(b*SS + c*128 + r))*EE + h*DHH + d0] =
                        make_float2(acc[mt][nt][half*2+0]*dinv, acc[mt][nt][half*2+1]*dinv);
                }
            }
    }
}

// ---------------- head projection ----------------
__global__ __launch_bounds__(64) void head_kernel(const float* __restrict__ hw, float* __restrict__ out)
{
    __shared__ float xs[EE];
    const int r = blockIdx.x, t = threadIdx.x;
    ((float4*)xs)[t]      = ((const float4*)(g_x + (size_t)r*EE))[t];
    ((float4*)xs)[t + 64] = ((const float4*)(g_x + (size_t)r*EE))[t + 64];
    __syncthreads();
    if (t < NVOC){
        float acc = 0.f;
        #pragma unroll 8
        for (int k = 0; k < EE; k++) acc += xs[k] * hw[k*NVOC + t];
        out[(size_t)r*NVOC + t] = acc;
    }
}

// ---------------- host launch ----------------
extern "C" void kernel_launch(void* const* d_in, const int* in_sizes, int n_in,
                              void* d_out, int out_size)
{
    (void)in_sizes; (void)n_in; (void)out_size;
    const int*   value = (const int*)  d_in[0];
    const int*   depth = (const int*)  d_in[1];
    const int*   pos   = (const int*)  d_in[2];
    const float* proj  = (const float*)d_in[3];
    const float* sos   = (const float*)d_in[4];
    const float* tok   = (const float*)d_in[5];
    const float* dep   = (const float*)d_in[6];
    const float* spa   = (const float*)d_in[7];
    const float* ln1w  = (const float*)d_in[8];
    const float* ln1b  = (const float*)d_in[9];
    const float* Wq    = (const float*)d_in[10];
    const float* bq    = (const float*)d_in[11];
    const float* Wk    = (const float*)d_in[12];
    const float* bk    = (const float*)d_in[13];
    const float* Wv    = (const float*)d_in[14];
    const float* bv    = (const float*)d_in[15];
    const float* Wo    = (const float*)d_in[16];
    const float* bo    = (const float*)d_in[17];
    const float* ln2w  = (const float*)d_in[18];
    const float* ln2b  = (const float*)d_in[19];
    const float* W1    = (const float*)d_in[20];
    const float* b1    = (const float*)d_in[21];
    const float* W2    = (const float*)d_in[22];
    const float* b2    = (const float*)d_in[23];
    const float* hw    = (const float*)d_in[24];

    float *px, *ph, *pq, *pk, *pv, *po, *pff;
    cudaGetSymbolAddress((void**)&px,  g_x);
    cudaGetSymbolAddress((void**)&ph,  g_h);
    cudaGetSymbolAddress((void**)&pq,  g_q);
    cudaGetSymbolAddress((void**)&pk,  g_k);
    cudaGetSymbolAddress((void**)&pv,  g_v);
    cudaGetSymbolAddress((void**)&po,  g_o);
    cudaGetSymbolAddress((void**)&pff, g_ff);

    cudaFuncSetAttribute(po_kernel, cudaFuncAttributeMaxDynamicSharedMemorySize, PO_SMEM_BYTES);

    embed_kernel<<<(BSR*EE + 255)/256, 256>>>(value, depth, pos, sos, tok, dep, spa);
    prep_proj_kernel<<<(LL*DHH*MMF + 255)/256, 256>>>(proj);

    dim3 g512(4, 32);
    dim3 g2048(16, 32);
    dim3 gqkv(4, 32, 3);
    dim3 gfeat(NCH, BHH, 2);
    dim3 gchunk(NCH, BHH);
    dim3 gprefix(8, BHH);

    for (int l = 0; l < LL; l++){
        ln_kernel<<<BSR, 128>>>(px, ph, ln1w + l*EE, ln1b + l*EE);
        qkv_kernel<<<gqkv, 256>>>(ph,
            Wq + (size_t)l*EE*EE, Wk + (size_t)l*EE*EE, Wv + (size_t)l*EE*EE,
            bq + l*EE, bk + l*EE, bv + l*EE,
            pq, pk, pv);

        feat_kernel<<<gfeat, 256>>>(l);
        kvz_kernel<<<gchunk, 256>>>(l);
        chunk_prefix_kernel<<<gprefix, 1024>>>();
        po_kernel<<<gchunk, 256, PO_SMEM_BYTES>>>();

        tgemm_kernel<<<g512, 256>>>(po, Wo + (size_t)l*EE*EE, bo + l*EE, px, px, EE, EE, 0);
        ln_kernel<<<BSR, 128>>>(px, ph, ln2w + l*EE, ln2b + l*EE);
        tgemm_kernel<<<g2048, 256>>>(ph, W1 + (size_t)l*EE*FFD, b1 + l*FFD, nullptr, pff, FFD, EE, 1);
        tgemm_kernel<<<g512, 256>>>(pff, W2 + (size_t)l*FFD*EE, b2 + l*EE, px, px, EE, FFD, 0);
    }

    head_kernel<<<BSR, 64>>>(hw, (float*)d_out);
}

// round 11
// speedup vs baseline: 1.2038x; 1.0868x over previous
#include <cuda_runtime.h>
#include <cuda_bf16.h>
#include <math.h>

// ---------------- problem constants ----------------
#define BB   2
#define SS   2048
#define EE   512
#define HH   8
#define LL   4
#define DHH  64
#define MMF  128
#define AAX  3
#define NVOC 17
#define BHH  (BB*HH)      // 16
#define BSR  (BB*SS)      // 4096
#define NCH  (SS/128)     // 16
#define FFD  (4*EE)       // 2048

#define DNQ   0.3535533905932738f
#define RATIO 0.08838834764831845f
#define KEPS  1e-4f
#define DEPS  1e-6f

// ---------------- scratch ----------------
__device__ float g_x [BSR*EE];
__device__ float g_h [BSR*EE];
__device__ float g_q [BSR*EE];
__device__ float g_k [BSR*EE];
__device__ float g_v [BSR*EE];
__device__ float g_o [BSR*EE];
__device__ float g_ff[BSR*FFD];
__device__ float g_qp[BHH*SS*MMF];
__device__ float g_kp[BHH*SS*MMF];
__device__ unsigned g_kmaxv[LL];
__device__ float g_Sc[BHH*NCH*MMF*DHH];
__device__ float g_Sp[BHH*NCH*MMF*DHH];
__device__ float g_zc[BHH*NCH*MMF];
__device__ float g_zp[BHH*NCH*MMF];
__device__ unsigned g_projh[LL*DHH*MMF];   // transposed [l][k][m], tf32 hi
__device__ unsigned g_projl[LL*DHH*MMF];   // transposed [l][k][m], tf32 lo

// ---------------- helpers ----------------
__device__ __forceinline__ unsigned f_enc(float f){
    unsigned u = __float_as_uint(f);
    return (u & 0x80000000u) ? ~u : (u | 0x80000000u);
}
__device__ __forceinline__ float f_dec(unsigned u){
    return (u & 0x80000000u) ? __uint_as_float(u & 0x7fffffffu) : __uint_as_float(~u);
}
__device__ __forceinline__ unsigned f2tf(float x){
    unsigned r; asm("cvt.rna.tf32.f32 %0, %1;" : "=r"(r) : "f"(x)); return r;
}
// A-row interleave: within each 16-row group store m0,m8,m1,m9,... so fragment
// row pairs (r, r+8) are adjacent -> LDS.64
__device__ __forceinline__ int permA(int m){
    return (m & ~15) | ((m & 7) << 1) | ((m >> 3) & 1);
}

#define MMA_TF32(c, a, b) asm volatile( \
  "mma.sync.aligned.m16n8k8.row.col.f32.tf32.tf32.f32 " \
  "{%0,%1,%2,%3}, {%4,%5,%6,%7}, {%8,%9}, {%0,%1,%2,%3};" \
  : "+f"(c[0]),"+f"(c[1]),"+f"(c[2]),"+f"(c[3]) \
  : "r"(a[0]),"r"(a[1]),"r"(a[2]),"r"(a[3]), "r"(b[0]),"r"(b[1]))

__device__ __forceinline__ void tfsplit(float x, unsigned& hi, unsigned& lo){
    hi = f2tf(x);
    lo = f2tf(x - __uint_as_float(hi));
}

// ---------------- embedding (+ per-layer kmax reset) ----------------
__global__ void embed_kernel(const int* __restrict__ value, const int* __restrict__ depth,
                             const int* __restrict__ pos,   const float* __restrict__ sos,
                             const float* __restrict__ tok, const float* __restrict__ dep,
                             const float* __restrict__ spa)
{
    if (blockIdx.x == 0 && threadIdx.x < LL) g_kmaxv[threadIdx.x] = 0u;
    int i = blockIdx.x * 256 + threadIdx.x;
    if (i >= BSR*EE) return;
    int e = i & (EE-1);
    int r = i >> 9;
    int b = r / SS, s = r - b*SS;
    float val;
    if (s == 0) val = sos[e];
    else {
        int p = b*SS + s - 1;
        val = tok[value[p]*EE + e] + dep[depth[p]*EE + e];
        #pragma unroll
        for (int a = 0; a < AAX; a++)
            val += spa[(size_t)a*65*EE + pos[p*AAX + a]*EE + e];
    }
    g_x[i] = val;
}

// ---------------- proj precompute: transposed hi/lo splits ----------------
__global__ void prep_proj_kernel(const float* __restrict__ proj)
{
    int i = blockIdx.x * 256 + threadIdx.x;      // i over LL*DHH*MMF
    if (i >= LL*DHH*MMF) return;
    int l = i / (DHH*MMF);
    int rem = i - l*(DHH*MMF);
    int k = rem >> 7;            // 0..63
    int m = rem & 127;           // 0..127
    float v = proj[(size_t)l*MMF*DHH + m*DHH + k];
    unsigned hi, lo; tfsplit(v, hi, lo);
    g_projh[i] = hi;
    g_projl[i] = lo;
}

// ---------------- layernorm ----------------
__global__ __launch_bounds__(128) void ln_kernel(const float* __restrict__ in, float* __restrict__ out,
                                                 const float* __restrict__ w, const float* __restrict__ bia)
{
    int r = blockIdx.x, t = threadIdx.x;
    const float4 v = ((const float4*)(in + (size_t)r*EE))[t];
    float s  = v.x + v.y + v.z + v.w;
    float sq = v.x*v.x + v.y*v.y + v.z*v.z + v.w*v.w;
    #pragma unroll
    for (int o = 16; o; o >>= 1){ s += __shfl_xor_sync(~0u, s, o); sq += __shfl_xor_sync(~0u, sq, o); }
    __shared__ float sh[8];
    if ((t & 31) == 0){ sh[t>>5] = s; sh[4 + (t>>5)] = sq; }
    __syncthreads();
    s  = sh[0]+sh[1]+sh[2]+sh[3];
    sq = sh[4]+sh[5]+sh[6]+sh[7];
    float mu  = s * (1.f/EE);
    float var = sq * (1.f/EE) - mu*mu;
    float rs  = rsqrtf(var + 1e-5f);
    float4 wv = ((const float4*)w)[t], bv = ((const float4*)bia)[t];
    float4 o4;
    o4.x = (v.x-mu)*rs*wv.x + bv.x;
    o4.y = (v.y-mu)*rs*wv.y + bv.y;
    o4.z = (v.z-mu)*rs*wv.z + bv.z;
    o4.w = (v.w-mu)*rs*wv.w + bv.w;
    ((float4*)(out + (size_t)r*EE))[t] = o4;
}

// ---------------- tf32 GEMM (weights) — interleaved A rows, LDS.64 A frags ----------------
#define BKK 16
#define LDA 136
#define LDB 136

__device__ __forceinline__ void gemm_body(
    const float* __restrict__ Am, const float* __restrict__ Bm,
    const float* __restrict__ bias, const float* __restrict__ resid,
    float* __restrict__ C, int N, int K, int kbase, int ksub, int act, int atomicf,
    unsigned* As, unsigned* Bs)
{
    const int tid = threadIdx.x;
    const int bm = blockIdx.y * 128, bn = blockIdx.x * 128;
    const int w = tid >> 5, lane = tid & 31;
    const int wm = (w & 1) * 64, wn = (w >> 1) * 32;
    const int lr = lane >> 2, lc = lane & 3;

    float acc[4][4][4];
    #pragma unroll
    for (int i = 0; i < 4; i++)
        #pragma unroll
        for (int j = 0; j < 4; j++)
            #pragma unroll
            for (int t = 0; t < 4; t++) acc[i][j][t] = 0.f;

    const int f0 = tid, f1 = tid + 256;
    const int ar0 = f0 >> 2, ak0 = (f0 & 3) << 2;
    const int ar1 = f1 >> 2, ak1 = (f1 & 3) << 2;
    const int br0 = f0 >> 5, bc0 = (f0 & 31) << 2;
    const int br1 = f1 >> 5, bc1 = (f1 & 31) << 2;
    const int pa0 = permA(ar0), pa1 = permA(ar1);

    float4 a4[2], b4[2];
    const int nk = ksub / BKK;

    a4[0] = *(const float4*)&Am[(size_t)(bm + ar0)*K + kbase + ak0];
    a4[1] = *(const float4*)&Am[(size_t)(bm + ar1)*K + kbase + ak1];
    b4[0] = *(const float4*)&Bm[(size_t)(kbase + br0)*N + bn + bc0];
    b4[1] = *(const float4*)&Bm[(size_t)(kbase + br1)*N + bn + bc1];
    {
        unsigned* Ab = As; unsigned* Bb = Bs;
        Ab[(ak0+0)*LDA + pa0] = f2tf(a4[0].x); Ab[(ak0+1)*LDA + pa0] = f2tf(a4[0].y);
        Ab[(ak0+2)*LDA + pa0] = f2tf(a4[0].z); Ab[(ak0+3)*LDA + pa0] = f2tf(a4[0].w);
        Ab[(ak1+0)*LDA + pa1] = f2tf(a4[1].x); Ab[(ak1+1)*LDA + pa1] = f2tf(a4[1].y);
        Ab[(ak1+2)*LDA + pa1] = f2tf(a4[1].z); Ab[(ak1+3)*LDA + pa1] = f2tf(a4[1].w);
        uint4 bv0 = make_uint4(f2tf(b4[0].x), f2tf(b4[0].y), f2tf(b4[0].z), f2tf(b4[0].w));
        uint4 bv1 = make_uint4(f2tf(b4[1].x), f2tf(b4[1].y), f2tf(b4[1].z), f2tf(b4[1].w));
        *(uint4*)&Bb[br0*LDB + bc0] = bv0;
        *(uint4*)&Bb[br1*LDB + bc1] = bv1;
    }
    __syncthreads();

    for (int it = 0; it < nk; it++){
        const int cur = it & 1;
        if (it + 1 < nk){
            const int k0 = kbase + (it + 1) * BKK;
            a4[0] = *(const float4*)&Am[(size_t)(bm + ar0)*K + k0 + ak0];
            a4[1] = *(const float4*)&Am[(size_t)(bm + ar1)*K + k0 + ak1];
            b4[0] = *(const float4*)&Bm[(size_t)(k0 + br0)*N + bn + bc0];
            b4[1] = *(const float4*)&Bm[(size_t)(k0 + br1)*N + bn + bc1];
        }
        {
            const unsigned* Ab = As + cur * (BKK * LDA);
            const unsigned* Bb = Bs + cur * (BKK * LDB);
            #pragma unroll
            for (int ks = 0; ks < BKK; ks += 8){
                unsigned af[4][4], bf[4][2];
                #pragma unroll
                for (int mt = 0; mt < 4; mt++){
                    const int base = (ks + lc)*LDA + wm + mt*16 + lr*2;
                    uint2 x0 = *(const uint2*)&Ab[base];
                    uint2 x1 = *(const uint2*)&Ab[base + 4*LDA];
                    af[mt][0] = x0.x; af[mt][1] = x0.y;
                    af[mt][2] = x1.x; af[mt][3] = x1.y;
                }
                #pragma unroll
                for (int nt = 0; nt < 4; nt++){
                    const int base = (ks + lc)*LDB + wn + nt*8 + lr;
                    bf[nt][0] = Bb[base];
                    bf[nt][1] = Bb[base + 4*LDB];
                }
                #pragma unroll
                for (int mt = 0; mt < 4; mt++)
                    #pragma unroll
                    for (int nt = 0; nt < 4; nt++)
                        MMA_TF32(acc[mt][nt], af[mt], bf[nt]);
            }
        }
        if (it + 1 < nk){
            unsigned* Ab = As + (cur ^ 1) * (BKK * LDA);
            unsigned* Bb = Bs + (cur ^ 1) * (BKK * LDB);
            Ab[(ak0+0)*LDA + pa0] = f2tf(a4[0].x); Ab[(ak0+1)*LDA + pa0] = f2tf(a4[0].y);
            Ab[(ak0+2)*LDA + pa0] = f2tf(a4[0].z); Ab[(ak0+3)*LDA + pa0] = f2tf(a4[0].w);
            Ab[(ak1+0)*LDA + pa1] = f2tf(a4[1].x); Ab[(ak1+1)*LDA + pa1] = f2tf(a4[1].y);
            Ab[(ak1+2)*LDA + pa1] = f2tf(a4[1].z); Ab[(ak1+3)*LDA + pa1] = f2tf(a4[1].w);
            uint4 bv0 = make_uint4(f2tf(b4[0].x), f2tf(b4[0].y), f2tf(b4[0].z), f2tf(b4[0].w));
            uint4 bv1 = make_uint4(f2tf(b4[1].x), f2tf(b4[1].y), f2tf(b4[1].z), f2tf(b4[1].w));
            *(uint4*)&Bb[br0*LDB + bc0] = bv0;
            *(uint4*)&Bb[br1*LDB + bc1] = bv1;
        }
        __syncthreads();
    }

    #pragma unroll
    for (int mt = 0; mt < 4; mt++){
        const int r0 = bm + wm + mt*16 + lr;
        #pragma unroll
        for (int nt = 0; nt < 4; nt++){
            const int c0 = bn + wn + nt*8 + 2*lc;
            const float bx = bias ? bias[c0] : 0.f;
            const float by = bias ? bias[c0+1] : 0.f;
            #pragma unroll
            for (int half = 0; half < 2; half++){
                const int r = r0 + half*8;
                float v0 = acc[mt][nt][half*2+0] + bx;
                float v1 = acc[mt][nt][half*2+1] + by;
                if (act){
                    v0 = 0.5f*v0*(1.f + erff(v0*0.70710678118654752f));
                    v1 = 0.5f*v1*(1.f + erff(v1*0.70710678118654752f));
                }
                if (atomicf){
                    atomicAdd(&C[(size_t)r*N + c0],     v0);
                    atomicAdd(&C[(size_t)r*N + c0 + 1], v1);
                } else {
                    if (resid){
                        v0 += resid[(size_t)r*N + c0];
                        v1 += resid[(size_t)r*N + c0+1];
                    }
                    *(float2*)&C[(size_t)r*N + c0] = make_float2(v0, v1);
                }
            }
        }
    }
}

__global__ __launch_bounds__(256, 2) void tgemm_kernel(
    const float* __restrict__ A, const float* __restrict__ Bm,
    const float* __restrict__ bias, const float* __restrict__ resid,
    float* __restrict__ C, int N, int K, int act)
{
    __shared__ __align__(16) unsigned As[2*BKK*LDA];
    __shared__ __align__(16) unsigned Bs[2*BKK*LDB];
    gemm_body(A, Bm, bias, resid, C, N, K, 0, K, act, 0, As, Bs);
}

// split-K=2, atomic accumulate into C (C already holds the residual).
// kh==0 carries the bias; no activation.
__global__ __launch_bounds__(256, 2) void tgemm_sk_kernel(
    const float* __restrict__ A, const float* __restrict__ Bm,
    const float* __restrict__ bias,
    float* __restrict__ C, int N, int K)
{
    __shared__ __align__(16) unsigned As[2*BKK*LDA];
    __shared__ __align__(16) unsigned Bs[2*BKK*LDB];
    const int kh = blockIdx.z;
    gemm_body(A, Bm, (kh == 0) ? bias : nullptr, nullptr,
              C, N, K, kh*(K/2), K/2, 0, 1, As, Bs);
}

__global__ __launch_bounds__(256, 2) void qkv_kernel(
    const float* __restrict__ A,
    const float* __restrict__ Wq, const float* __restrict__ Wk, const float* __restrict__ Wv,
    const float* __restrict__ bq, const float* __restrict__ bk, const float* __restrict__ bv,
    float* __restrict__ oq, float* __restrict__ ok, float* __restrict__ ov)
{
    __shared__ __align__(16) unsigned As[2*BKK*LDA];
    __shared__ __align__(16) unsigned Bs[2*BKK*LDB];
    const int z = blockIdx.z;
    const float* Bm  = (z == 0) ? Wq : (z == 1) ? Wk : Wv;
    const float* bi  = (z == 0) ? bq : (z == 1) ? bk : bv;
    float*       Cm  = (z == 0) ? oq : (z == 1) ? ok : ov;
    gemm_body(A, Bm, bi, nullptr, Cm, EE, EE, 0, EE, 0, 0, As, Bs);
}

// helper: load interleaved hi/lo A fragments (LDS.64 pairs)
#define LOAD_AFRAG(afh, afl, Ah, Al, base) do { \
    uint2 _h0 = *(const uint2*)&(Ah)[(base)]; \
    uint2 _h1 = *(const uint2*)&(Ah)[(base) + 4*LDA]; \
    uint2 _l0 = *(const uint2*)&(Al)[(base)]; \
    uint2 _l1 = *(const uint2*)&(Al)[(base) + 4*LDA]; \
    (afh)[0] = _h0.x; (afh)[1] = _h0.y; (afh)[2] = _h1.x; (afh)[3] = _h1.y; \
    (afl)[0] = _l0.x; (afl)[1] = _l0.y; (afl)[2] = _l1.x; (afl)[3] = _l1.y; \
} while(0)

// ================= FAVOR features via 3xTF32 MMA (precomputed proj splits) ===========
__global__ __launch_bounds__(256, 2) void feat_kernel(int l)
{
    __shared__ __align__(16) unsigned Ah[16*LDA], Al[16*LDA], Bh[16*LDB], Bl[16*LDB];
    __shared__ float diag[128];
    __shared__ unsigned rmax[128];
    __shared__ unsigned bmax;
    const int tid = threadIdx.x;
    const int c = blockIdx.x, bh = blockIdx.y;
    const int isq = (blockIdx.z == 0);
    const int b = bh / HH, h = bh % HH;
    const float* src = isq ? g_q : g_k;
    const unsigned* prjh = g_projh + (size_t)l*DHH*MMF;
    const unsigned* prjl = g_projl + (size_t)l*DHH*MMF;
    const int w = tid >> 5, lane = tid & 31;
    const int wm = (w & 1) * 64, wn = (w >> 1) * 32;
    const int lr = lane >> 2, lc = lane & 3;

    if (tid < 128) rmax[tid] = 0u;
    if (tid == 0) bmax = 0u;

    float acc[4][4][4];
    #pragma unroll
    for (int i = 0; i < 4; i++)
        #pragma unroll
        for (int j = 0; j < 4; j++)
            #pragma unroll
            for (int t = 0; t < 4; t++) acc[i][j][t] = 0.f;

    const int rrow = tid >> 1, kg = (tid & 1) * 8;
    const int prow = permA(rrow);
    const int bk = tid >> 4, bm0 = (tid & 15) * 8;     // B staging (transposed layout)
    float sq = 0.f;

    for (int kit = 0; kit < 4; kit++){
        const int k0 = kit * 16;
        // A: x rows (scaled) — staged k-major with tfsplit, interleaved m
        #pragma unroll
        for (int q4 = 0; q4 < 2; q4++){
            float4 a = *(const float4*)&src[((size_t)(b*SS + c*128 + rrow))*EE + h*DHH + k0 + kg + q4*4];
            float vals[4] = {a.x*DNQ, a.y*DNQ, a.z*DNQ, a.w*DNQ};
            #pragma unroll
            for (int i = 0; i < 4; i++){
                sq += vals[i]*vals[i];
                unsigned hi, lo; tfsplit(vals[i], hi, lo);
                Ah[(kg + q4*4 + i)*LDA + prow] = hi;
                Al[(kg + q4*4 + i)*LDA + prow] = lo;
            }
        }
        // B: precomputed transposed hi/lo proj — vector copies
        {
            const size_t pb = (size_t)(k0 + bk)*MMF + bm0;
            uint4 h0 = *(const uint4*)&prjh[pb];
            uint4 h1 = *(const uint4*)&prjh[pb + 4];
            uint4 l0 = *(const uint4*)&prjl[pb];
            uint4 l1 = *(const uint4*)&prjl[pb + 4];
            *(uint4*)&Bh[bk*LDB + bm0]     = h0;
            *(uint4*)&Bh[bk*LDB + bm0 + 4] = h1;
            *(uint4*)&Bl[bk*LDB + bm0]     = l0;
            *(uint4*)&Bl[bk*LDB + bm0 + 4] = l1;
        }
        __syncthreads();
        #pragma unroll
        for (int ks = 0; ks < 16; ks += 8){
            unsigned afh[4][4], afl[4][4], bfh[4][2], bfl[4][2];
            #pragma unroll
            for (int mt = 0; mt < 4; mt++){
                const int base = (ks + lc)*LDA + wm + mt*16 + lr*2;
                LOAD_AFRAG(afh[mt], afl[mt], Ah, Al, base);
            }
            #pragma unroll
            for (int nt = 0; nt < 4; nt++){
                const int base = (ks + lc)*LDB + wn + nt*8 + lr;
                bfh[nt][0] = Bh[base];         bfl[nt][0] = Bl[base];
                bfh[nt][1] = Bh[base + 4*LDB]; bfl[nt][1] = Bl[base + 4*LDB];
            }
            #pragma unroll
            for (int mt = 0; mt < 4; mt++)
                #pragma unroll
                for (int nt = 0; nt < 4; nt++){
                    MMA_TF32(acc[mt][nt], afh[mt], bfh[nt]);
                    MMA_TF32(acc[mt][nt], afh[mt], bfl[nt]);
                    MMA_TF32(acc[mt][nt], afl[mt], bfh[nt]);
                }
        }
        __syncthreads();
    }
    {
        float other = __shfl_xor_sync(~0u, sq, 1);
        if ((tid & 1) == 0) diag[rrow] = 0.5f * (sq + other);
    }
    if (isq){
        #pragma unroll
        for (int mt = 0; mt < 4; mt++)
            #pragma unroll
            for (int half = 0; half < 2; half++){
                const int r = wm + mt*16 + lr + half*8;
                float m = -3.4e38f;
                #pragma unroll
                for (int nt = 0; nt < 4; nt++){
                    m = fmaxf(m, acc[mt][nt][half*2+0]);
                    m = fmaxf(m, acc[mt][nt][half*2+1]);
                }
                atomicMax(&rmax[r], f_enc(m));
            }
    } else {
        float m = -3.4e38f;
        #pragma unroll
        for (int mt = 0; mt < 4; mt++)
            #pragma unroll
            for (int nt = 0; nt < 4; nt++)
                #pragma unroll
                for (int t = 0; t < 4; t++) m = fmaxf(m, acc[mt][nt][t]);
        #pragma unroll
        for (int o = 16; o; o >>= 1) m = fmaxf(m, __shfl_xor_sync(~0u, m, o));
        if (lane == 0) atomicMax(&bmax, f_enc(m));
    }
    __syncthreads();

    const size_t qbase = (size_t)bh*SS + c*128;
    if (isq){
        #pragma unroll
        for (int mt = 0; mt < 4; mt++)
            #pragma unroll
            for (int half = 0; half < 2; half++){
                const int r = wm + mt*16 + lr + half*8;
                const float dg = diag[r], mx = f_dec(rmax[r]);
                #pragma unroll
                for (int nt = 0; nt < 4; nt++){
                    const int c0 = wn + nt*8 + 2*lc;
                    float v0 = RATIO*(expf(acc[mt][nt][half*2+0] - dg - mx) + KEPS);
                    float v1 = RATIO*(expf(acc[mt][nt][half*2+1] - dg - mx) + KEPS);
                    *(float2*)&g_qp[(qbase + r)*MMF + c0] = make_float2(v0, v1);
                }
            }
    } else {
        if (tid == 0) atomicMax(&g_kmaxv[l], bmax);
        #pragma unroll
        for (int mt = 0; mt < 4; mt++)
            #pragma unroll
            for (int half = 0; half < 2; half++){
                const int r = wm + mt*16 + lr + half*8;
                const float dg = diag[r];
                #pragma unroll
                for (int nt = 0; nt < 4; nt++){
                    const int c0 = wn + nt*8 + 2*lc;
                    float v0 = acc[mt][nt][half*2+0] - dg;
                    float v1 = acc[mt][nt][half*2+1] - dg;
                    *(float2*)&g_kp[(qbase + r)*MMF + c0] = make_float2(v0, v1);
                }
            }
    }
}

// ========== fused: kp exp-transform + writeback + zc + Sc (3xTF32 MMA) ==========
#define KVLDB 72
__global__ __launch_bounds__(256, 2) void kvz_kernel(int l)
{
    __shared__ __align__(16) unsigned Ah[16*LDA], Al[16*LDA], Bh[16*KVLDB], Bl[16*KVLDB];
    __shared__ float zcs[128];
    const int c = blockIdx.x, bh = blockIdx.y;
    const int b = bh / HH, h = bh % HH;
    const int tid = threadIdx.x;
    const int w = tid >> 5, lane = tid & 31;
    const int wm = (w & 1) * 64, wn = (w >> 1) * 16;
    const int lr = lane >> 2, lc = lane & 3;
    const size_t qbase = (size_t)bh*SS + c*128;
    const float gm = f_dec(g_kmaxv[l]);

    if (tid < 128) zcs[tid] = 0.f;

    float acc[4][2][4];
    #pragma unroll
    for (int i = 0; i < 4; i++)
        #pragma unroll
        for (int j = 0; j < 2; j++)
            #pragma unroll
            for (int t = 0; t < 4; t++) acc[i][j][t] = 0.f;

    const int at = tid >> 4, am0 = (tid & 15) * 8;
    const int bt = tid >> 4, bd0 = (tid & 15) * 4;
    float zcp[8];
    #pragma unroll
    for (int i = 0; i < 8; i++) zcp[i] = 0.f;

    for (int kit = 0; kit < 8; kit++){
        const int t0 = kit * 16;
        #pragma unroll
        for (int q4 = 0; q4 < 2; q4++){
            size_t off = (qbase + t0 + at)*MMF + am0 + q4*4;
            float4 a = *(const float4*)&g_kp[off];
            float vals[4];
            vals[0] = RATIO*(expf(a.x - gm) + KEPS);
            vals[1] = RATIO*(expf(a.y - gm) + KEPS);
            vals[2] = RATIO*(expf(a.z - gm) + KEPS);
            vals[3] = RATIO*(expf(a.w - gm) + KEPS);
            *(float4*)&g_kp[off] = make_float4(vals[0], vals[1], vals[2], vals[3]);
            #pragma unroll
            for (int i = 0; i < 4; i++){
                zcp[q4*4 + i] += vals[i];
                unsigned hi, lo; tfsplit(vals[i], hi, lo);
                const int pm = permA(am0 + q4*4 + i);
                Ah[at*LDA + pm] = hi;
                Al[at*LDA + pm] = lo;
            }
        }
        {
            float4 vv = *(const float4*)&g_v[((size_t)(b*SS + c*128 + t0 + bt))*EE + h*DHH + bd0];
            float vals[4] = {vv.x, vv.y, vv.z, vv.w};
            #pragma unroll
            for (int i = 0; i < 4; i++){
                unsigned hi, lo; tfsplit(vals[i], hi, lo);
                Bh[bt*KVLDB + bd0 + i] = hi;
                Bl[bt*KVLDB + bd0 + i] = lo;
            }
        }
        __syncthreads();
        #pragma unroll
        for (int ks = 0; ks < 16; ks += 8){
            unsigned afh[4][4], afl[4][4], bfh[2][2], bfl[2][2];
            #pragma unroll
            for (int mt = 0; mt < 4; mt++){
                const int base = (ks + lc)*LDA + wm + mt*16 + lr*2;
                LOAD_AFRAG(afh[mt], afl[mt], Ah, Al, base);
            }
            #pragma unroll
            for (int nt = 0; nt < 2; nt++){
                const int base = (ks + lc)*KVLDB + wn + nt*8 + lr;
                bfh[nt][0] = Bh[base];           bfl[nt][0] = Bl[base];
                bfh[nt][1] = Bh[base + 4*KVLDB]; bfl[nt][1] = Bl[base + 4*KVLDB];
            }
            #pragma unroll
            for (int mt = 0; mt < 4; mt++)
                #pragma unroll
                for (int nt = 0; nt < 2; nt++){
                    MMA_TF32(acc[mt][nt], afh[mt], bfh[nt]);
                    MMA_TF32(acc[mt][nt], afh[mt], bfl[nt]);
                    MMA_TF32(acc[mt][nt], afl[mt], bfh[nt]);
                }
        }
        __syncthreads();
    }
    #pragma unroll
    for (int i = 0; i < 8; i++) atomicAdd(&zcs[am0 + i], zcp[i]);
    __syncthreads();
    if (tid < 128) g_zc[(bh*NCH + c)*MMF + tid] = zcs[tid];

    const size_t base = ((size_t)(bh*NCH + c))*MMF;
    #pragma unroll
    for (int mt = 0; mt < 4; mt++)
        #pragma unroll
        for (int half = 0; half < 2; half++){
            const int m = wm + mt*16 + lr + half*8;
            #pragma unroll
            for (int nt = 0; nt < 2; nt++){
                const int d0 = wn + nt*8 + 2*lc;
                *(float2*)&g_Sc[(base + m)*DHH + d0] =
                    make_float2(acc[mt][nt][half*2+0], acc[mt][nt][half*2+1]);
            }
        }
}

// ---------------- parallel exclusive prefix over chunks ----------------
__global__ __launch_bounds__(1024) void chunk_prefix_kernel()
{
    const int bh = blockIdx.y;
    const int idx = blockIdx.x * 1024 + threadIdx.x;
    float run = 0.f;
    #pragma unroll
    for (int c = 0; c < NCH; c++){
        size_t off = ((size_t)(bh*NCH + c))*MMF*DHH + idx;
        float v = g_Sc[off];
        g_Sp[off] = run;
        run += v;
    }
    if (blockIdx.x == 0 && threadIdx.x < MMF){
        const int m = threadIdx.x;
        float rz = 0.f;
        #pragma unroll
        for (int c = 0; c < NCH; c++){
            int zb = (bh*NCH + c)*MMF + m;
            g_zp[zb] = rz;
            rz += g_zc[zb];
        }
    }
}

// ======= FUSED: P = mask(qp@kp^T) in smem, then out = ([P|qp]@[v;Sp])/den =======
#define LDP 132
#define PO_PS_WORDS (128*LDP)          // 16896
#define PO_AB_WORDS (16*LDA)           // 2176
#define PO_SMEM_BYTES ((PO_PS_WORDS + 4*PO_AB_WORDS + 128) * 4)   // 102912 B

__global__ __launch_bounds__(256) void po_kernel()
{
    extern __shared__ __align__(16) float po_smem[];
    float*    Ps    = po_smem;
    unsigned* Ah    = (unsigned*)(po_smem + PO_PS_WORDS);
    unsigned* Al    = Ah + PO_AB_WORDS;
    unsigned* Bh    = Al + PO_AB_WORDS;
    unsigned* Bl    = Bh + PO_AB_WORDS;
    float*    densh = (float*)(Bl + PO_AB_WORDS);

    const int c = blockIdx.x, bh = blockIdx.y;
    const int b = bh / HH, h = bh % HH;
    const int tid = threadIdx.x;
    const int w = tid >> 5, lane = tid & 31;
    const int wm = (w & 1) * 64;
    const int wnp = (w >> 1) * 32;
    const int wno = (w >> 1) * 16;
    const int lr = lane >> 2, lc = lane & 3;
    const size_t qbase = (size_t)bh*SS + c*128;
    const size_t sbase = ((size_t)(bh*NCH + c))*MMF;
    const int rrow = tid >> 1, kg = (tid & 1) * 8;
    const int prow = permA(rrow);

    // ---------------- phase 1: P = mask(qp @ kp^T) ----------------
    {
        float acc[4][4][4];
        #pragma unroll
        for (int i = 0; i < 4; i++)
            #pragma unroll
            for (int j = 0; j < 4; j++)
                #pragma unroll
                for (int t = 0; t < 4; t++) acc[i][j][t] = 0.f;

        for (int kit = 0; kit < 8; kit++){
            const int m0 = kit * 16;
            #pragma unroll
            for (int q4 = 0; q4 < 2; q4++){
                float4 a = *(const float4*)&g_qp[(qbase + rrow)*MMF + m0 + kg + q4*4];
                float va[4] = {a.x, a.y, a.z, a.w};
                float4 bk = *(const float4*)&g_kp[(qbase + rrow)*MMF + m0 + kg + q4*4];
                float vb[4] = {bk.x, bk.y, bk.z, bk.w};
                #pragma unroll
                for (int i = 0; i < 4; i++){
                    unsigned hi, lo;
                    tfsplit(va[i], hi, lo);
                    Ah[(kg + q4*4 + i)*LDA + prow] = hi;
                    Al[(kg + q4*4 + i)*LDA + prow] = lo;
                    tfsplit(vb[i], hi, lo);
                    Bh[(kg + q4*4 + i)*LDB + rrow] = hi;
                    Bl[(kg + q4*4 + i)*LDB + rrow] = lo;
                }
            }
            __syncthreads();
            #pragma unroll
            for (int ks = 0; ks < 16; ks += 8){
                unsigned afh[4][4], afl[4][4], bfh[4][2], bfl[4][2];
                #pragma unroll
                for (int mt = 0; mt < 4; mt++){
                    const int base = (ks + lc)*LDA + wm + mt*16 + lr*2;
                    LOAD_AFRAG(afh[mt], afl[mt], Ah, Al, base);
                }
                #pragma unroll
                for (int nt = 0; nt < 4; nt++){
                    const int base = (ks + lc)*LDB + wnp + nt*8 + lr;
                    bfh[nt][0] = Bh[base];         bfl[nt][0] = Bl[base];
                    bfh[nt][1] = Bh[base + 4*LDB]; bfl[nt][1] = Bl[base + 4*LDB];
                }
                #pragma unroll
                for (int mt = 0; mt < 4; mt++)
                    #pragma unroll
                    for (int nt = 0; nt < 4; nt++){
                        MMA_TF32(acc[mt][nt], afh[mt], bfh[nt]);
                        MMA_TF32(acc[mt][nt], afh[mt], bfl[nt]);
                        MMA_TF32(acc[mt][nt], afl[mt], bfh[nt]);
                    }
            }
            __syncthreads();
        }
        #pragma unroll
        for (int mt = 0; mt < 4; mt++)
            #pragma unroll
            for (int half = 0; half < 2; half++){
                const int r = wm + mt*16 + lr + half*8;
                #pragma unroll
                for (int nt = 0; nt < 4; nt++){
                    const int c0 = wnp + nt*8 + 2*lc;
                    float v0 = (c0   <= r) ? acc[mt][nt][half*2+0] : 0.f;
                    float v1 = (c0+1 <= r) ? acc[mt][nt][half*2+1] : 0.f;
                    *(float2*)&Ps[r*LDP + c0] = make_float2(v0, v1);
                }
            }
    }
    __syncthreads();

    // ------- phase 2: out = ([P|qp] @ [v;Sp]) / den, den fused in staging -------
    {
        float acc[4][2][4];
        #pragma unroll
        for (int i = 0; i < 4; i++)
            #pragma unroll
            for (int j = 0; j < 2; j++)
                #pragma unroll
                for (int t = 0; t < 4; t++) acc[i][j][t] = 0.f;

        const int bt = tid >> 4, bd0 = (tid & 15) * 4;
        float denp = 0.f;

        for (int kit = 0; kit < 16; kit++){
            const int j0 = kit * 16;
            #pragma unroll
            for (int q4 = 0; q4 < 2; q4++){
                float4 a;
                if (j0 < 128) a = *(const float4*)&Ps[rrow*LDP + j0 + kg + q4*4];
                else          a = *(const float4*)&g_qp[(qbase + rrow)*MMF + (j0 - 128) + kg + q4*4];
                float vals[4] = {a.x, a.y, a.z, a.w};
                if (j0 < 128){
                    denp += vals[0] + vals[1] + vals[2] + vals[3];
                } else {
                    float4 zpv = *(const float4*)&g_zp[sbase + (j0 - 128) + kg + q4*4];
                    denp += vals[0]*zpv.x + vals[1]*zpv.y + vals[2]*zpv.z + vals[3]*zpv.w;
                }
                #pragma unroll
                for (int i = 0; i < 4; i++){
                    unsigned hi, lo; tfsplit(vals[i], hi, lo);
                    Ah[(kg + q4*4 + i)*LDA + prow] = hi;
                    Al[(kg + q4*4 + i)*LDA + prow] = lo;
                }
            }
            {
                float4 hv;
                if (j0 < 128) hv = *(const float4*)&g_v[((size_t)(b*SS + c*128 + j0 + bt))*EE + h*DHH + bd0];
                else          hv = *(const float4*)&g_Sp[(sbase + (j0 - 128) + bt)*DHH + bd0];
                float vals[4] = {hv.x, hv.y, hv.z, hv.w};
                #pragma unroll
                for (int i = 0; i < 4; i++){
                    unsigned hi, lo; tfsplit(vals[i], hi, lo);
                    Bh[bt*KVLDB + bd0 + i] = hi;
                    Bl[bt*KVLDB + bd0 + i] = lo;
                }
            }
            __syncthreads();
            #pragma unroll
            for (int ks = 0; ks < 16; ks += 8){
                unsigned afh[4][4], afl[4][4], bfh[2][2], bfl[2][2];
                #pragma unroll
                for (int mt = 0; mt < 4; mt++){
                    const int base = (ks + lc)*LDA + wm + mt*16 + lr*2;
                    LOAD_AFRAG(afh[mt], afl[mt], Ah, Al, base);
                }
                #pragma unroll
                for (int nt = 0; nt < 2; nt++){
                    const int base = (ks + lc)*KVLDB + wno + nt*8 + lr;
                    bfh[nt][0] = Bh[base];           bfl[nt][0] = Bl[base];
                    bfh[nt][1] = Bh[base + 4*KVLDB]; bfl[nt][1] = Bl[base + 4*KVLDB];
                }
                #pragma unroll
                for (int mt = 0; mt < 4; mt++)
                    #pragma unroll
                    for (int nt = 0; nt < 2; nt++){
                        MMA_TF32(acc[mt][nt], afh[mt], bfh[nt]);
                        MMA_TF32(acc[mt][nt], afh[mt], bfl[nt]);
                        MMA_TF32(acc[mt][nt], afl[mt], bfh[nt]);
                    }
            }
            __syncthreads();
        }
        denp += __shfl_xor_sync(~0u, denp, 1);
        if ((tid & 1) == 0) densh[rrow] = denp;
        __syncthreads();

        #pragma unroll
        for (int mt = 0; mt < 4; mt++)
            #pragma unroll
            for (int half = 0; half < 2; half++){
                const int r = wm + mt*16 + lr + half*8;
                const float dinv = 1.f / (densh[r] + DEPS);
                #pragma unroll
                for (int nt = 0; nt < 2; nt++){
                    const int d0 = wno + nt*8 + 2*lc;
                    *(float2*)&g_o[((size_t)(b*SS + c*128 + r))*EE + h*DHH + d0] =
                        make_float2(acc[mt][nt][half*2+0]*dinv, acc[mt][nt][half*2+1]*dinv);
                }
            }
    }
}

// ---------------- head projection ----------------
__global__ __launch_bounds__(64) void head_kernel(const float* __restrict__ hw, float* __restrict__ out)
{
    __shared__ float xs[EE];
    const int r = blockIdx.x, t = threadIdx.x;
    ((float4*)xs)[t]      = ((const float4*)(g_x + (size_t)r*EE))[t];
    ((float4*)xs)[t + 64] = ((const float4*)(g_x + (size_t)r*EE))[t + 64];
    __syncthreads();
    if (t < NVOC){
        float acc = 0.f;
        #pragma unroll 8
        for (int k = 0; k < EE; k++) acc += xs[k] * hw[k*NVOC + t];
        out[(size_t)r*NVOC + t] = acc;
    }
}

// ---------------- host launch ----------------
extern "C" void kernel_launch(void* const* d_in, const int* in_sizes, int n_in,
                              void* d_out, int out_size)
{
    (void)in_sizes; (void)n_in; (void)out_size;
    const int*   value = (const int*)  d_in[0];
    const int*   depth = (const int*)  d_in[1];
    const int*   pos   = (const int*)  d_in[2];
    const float* proj  = (const float*)d_in[3];
    const float* sos   = (const float*)d_in[4];
    const float* tok   = (const float*)d_in[5];
    const float* dep   = (const float*)d_in[6];
    const float* spa   = (const float*)d_in[7];
    const float* ln1w  = (const float*)d_in[8];
    const float* ln1b  = (const float*)d_in[9];
    const float* Wq    = (const float*)d_in[10];
    const float* bq    = (const float*)d_in[11];
    const float* Wk    = (const float*)d_in[12];
    const float* bk    = (const float*)d_in[13];
    const float* Wv    = (const float*)d_in[14];
    const float* bv    = (const float*)d_in[15];
    const float* Wo    = (const float*)d_in[16];
    const float* bo    = (const float*)d_in[17];
    const float* ln2w  = (const float*)d_in[18];
    const float* ln2b  = (const float*)d_in[19];
    const float* W1    = (const float*)d_in[20];
    const float* b1    = (const float*)d_in[21];
    const float* W2    = (const float*)d_in[22];
    const float* b2    = (const float*)d_in[23];
    const float* hw    = (const float*)d_in[24];

    float *px, *ph, *pq, *pk, *pv, *po, *pff;
    cudaGetSymbolAddress((void**)&px,  g_x);
    cudaGetSymbolAddress((void**)&ph,  g_h);
    cudaGetSymbolAddress((void**)&pq,  g_q);
    cudaGetSymbolAddress((void**)&pk,  g_k);
    cudaGetSymbolAddress((void**)&pv,  g_v);
    cudaGetSymbolAddress((void**)&po,  g_o);
    cudaGetSymbolAddress((void**)&pff, g_ff);

    cudaFuncSetAttribute(po_kernel, cudaFuncAttributeMaxDynamicSharedMemorySize, PO_SMEM_BYTES);

    embed_kernel<<<(BSR*EE + 255)/256, 256>>>(value, depth, pos, sos, tok, dep, spa);
    prep_proj_kernel<<<(LL*DHH*MMF + 255)/256, 256>>>(proj);

    dim3 g512(4, 32);
    dim3 g2048(16, 32);
    dim3 gqkv(4, 32, 3);
    dim3 gsk(4, 32, 2);
    dim3 gfeat(NCH, BHH, 2);
    dim3 gchunk(NCH, BHH);
    dim3 gprefix(8, BHH);

    for (int l = 0; l < LL; l++){
        ln_kernel<<<BSR, 128>>>(px, ph, ln1w + l*EE, ln1b + l*EE);
        qkv_kernel<<<gqkv, 256>>>(ph,
            Wq + (size_t)l*EE*EE, Wk + (size_t)l*EE*EE, Wv + (size_t)l*EE*EE,
            bq + l*EE, bk + l*EE, bv + l*EE,
            pq, pk, pv);

        feat_kernel<<<gfeat, 256>>>(l);
        kvz_kernel<<<gchunk, 256>>>(l);
        chunk_prefix_kernel<<<gprefix, 1024>>>();
        po_kernel<<<gchunk, 256, PO_SMEM_BYTES>>>();

        // x += o @ Wo + bo   (split-K=2, atomic accumulate into x)
        tgemm_sk_kernel<<<gsk, 256>>>(po, Wo + (size_t)l*EE*EE, bo + l*EE, px, EE, EE);
        ln_kernel<<<BSR, 128>>>(px, ph, ln2w + l*EE, ln2b + l*EE);
        tgemm_kernel<<<g2048, 256>>>(ph, W1 + (size_t)l*EE*FFD, b1 + l*FFD, nullptr, pff, FFD, EE, 1);
        // x += gelu(ff) @ W2 + b2  (split-K=2, atomic accumulate into x)
        tgemm_sk_kernel<<<gsk, 256>>>(pff, W2 + (size_t)l*FFD*EE, b2 + l*EE, px, EE, FFD);
    }

    head_kernel<<<BSR, 64>>>(hw, (float*)d_out);
}